// round 3
// baseline (speedup 1.0000x reference)
#include <cuda_runtime.h>
#include <cuda_bf16.h>
#include <cstdint>

// Problem constants
#define BB   2
#define SS   1024
#define DD   2048
#define QH   32
#define KH   8
#define HD   64
#define MTOT (BB*SS)        // 2048 rows

// ---------------- scratch (device globals: allocation-free) ----------------
__device__ float g_Qp[MTOT * DD];          // [2048][2048]
__device__ float g_Kp[MTOT * KH * HD];     // [2048][512]
__device__ float g_Vp[MTOT * KH * HD];     // [2048][512]
__device__ float g_Ao[MTOT * DD];          // [2048][2048]

// ============================================================================
// Tensor-core GEMM: C[M,N] = A[M,K] @ W[K,N] + bias, fp32 in/out.
// bf16 3-pass split: a=ah+al, b=bh+bl; ah*bh + ah*bl + al*bh (fp32 accum).
// Block tile 128x128, BK=32, 8 warps of 64x32. blockIdx.z selects weight set.
// ============================================================================
#define BM 128
#define BN 128
#define BK 32
#define KSTR 40   // smem k-stride (bf16 elems): 80B rows, conflict-free ldmatrix

__device__ __forceinline__ void ldmx4(uint32_t* r, const void* p) {
    uint32_t addr = (uint32_t)__cvta_generic_to_shared(p);
    asm volatile("ldmatrix.sync.aligned.m8n8.x4.shared.b16 {%0,%1,%2,%3}, [%4];"
                 : "=r"(r[0]), "=r"(r[1]), "=r"(r[2]), "=r"(r[3]) : "r"(addr));
}

__device__ __forceinline__ void mma16816(float* c, const uint32_t* a, const uint32_t* b) {
    asm volatile("mma.sync.aligned.m16n8k16.row.col.f32.bf16.bf16.f32 "
                 "{%0,%1,%2,%3}, {%4,%5,%6,%7}, {%8,%9}, {%0,%1,%2,%3};"
                 : "+f"(c[0]), "+f"(c[1]), "+f"(c[2]), "+f"(c[3])
                 : "r"(a[0]), "r"(a[1]), "r"(a[2]), "r"(a[3]),
                   "r"(b[0]), "r"(b[1]));
}

__device__ __forceinline__ void split_bf16(float v, __nv_bfloat16& h, __nv_bfloat16& l) {
    h = __float2bfloat16_rn(v);
    l = __float2bfloat16_rn(v - __bfloat162float(h));
}

__global__ __launch_bounds__(256, 2)
void gemm_tc(const float* __restrict__ A,
             const float* __restrict__ W0, const float* __restrict__ b0, float* __restrict__ C0,
             const float* __restrict__ W1, const float* __restrict__ b1, float* __restrict__ C1,
             int M, int N, int K)
{
    const float* W    = blockIdx.z ? W1 : W0;
    const float* bias = blockIdx.z ? b1 : b0;
    float*       C    = blockIdx.z ? C1 : C0;

    __shared__ __nv_bfloat16 sAh[BM][KSTR], sAl[BM][KSTR];
    __shared__ __nv_bfloat16 sBh[BN][KSTR], sBl[BN][KSTR];   // TRANSPOSED: [n][k]

    const int tid  = threadIdx.x;
    const int lane = tid & 31;
    const int wid  = tid >> 5;
    const int wm   = wid & 1;      // 2 warp-rows (64 rows each)
    const int wn   = wid >> 1;     // 4 warp-cols (32 cols each)
    const int row0 = blockIdx.y * BM;
    const int col0 = blockIdx.x * BN;

    float acc[4][4][4];
#pragma unroll
    for (int i = 0; i < 4; i++)
#pragma unroll
        for (int j = 0; j < 4; j++)
#pragma unroll
            for (int k = 0; k < 4; k++) acc[i][j][k] = 0.f;

    // ldmatrix lane-addressing offsets
    const int a_r = lane & 15;
    const int a_k = (lane >> 4) << 3;                    // 0 / 8
    const int b_r = (lane & 7) | ((lane & 16) >> 1);     // n offset 0..15
    const int b_k = lane & 8;                            // 0 / 8

    // gmem load mappings
    const int alc = (tid & 7) * 4;    // A: k-offset within tile
    const int alr = tid >> 3;         // A: row 0..31 (4 passes of 32)
    const int bln = (tid & 31) * 4;   // B: n-offset
    const int blk = tid >> 5;         // B: k-row 0..7 (4 passes of 8)

    for (int kt = 0; kt < K; kt += BK) {
        // ---- stage A tile (convert + split) ----
#pragma unroll
        for (int p = 0; p < 4; p++) {
            int r = alr + p * 32;
            float4 v = *(const float4*)&A[(size_t)(row0 + r) * K + kt + alc];
            __nv_bfloat16 h0, l0, h1, l1, h2, l2, h3, l3;
            split_bf16(v.x, h0, l0); split_bf16(v.y, h1, l1);
            split_bf16(v.z, h2, l2); split_bf16(v.w, h3, l3);
            *(__nv_bfloat162*)&sAh[r][alc]     = __halves2bfloat162(h0, h1);
            *(__nv_bfloat162*)&sAh[r][alc + 2] = __halves2bfloat162(h2, h3);
            *(__nv_bfloat162*)&sAl[r][alc]     = __halves2bfloat162(l0, l1);
            *(__nv_bfloat162*)&sAl[r][alc + 2] = __halves2bfloat162(l2, l3);
        }
        // ---- stage B tile (convert + split + transpose) ----
#pragma unroll
        for (int p = 0; p < 4; p++) {
            int k = blk + p * 8;
            float4 v = *(const float4*)&W[(size_t)(kt + k) * N + col0 + bln];
            __nv_bfloat16 h, l;
            split_bf16(v.x, h, l); sBh[bln + 0][k] = h; sBl[bln + 0][k] = l;
            split_bf16(v.y, h, l); sBh[bln + 1][k] = h; sBl[bln + 1][k] = l;
            split_bf16(v.z, h, l); sBh[bln + 2][k] = h; sBl[bln + 2][k] = l;
            split_bf16(v.w, h, l); sBh[bln + 3][k] = h; sBl[bln + 3][k] = l;
        }
        __syncthreads();

#pragma unroll
        for (int kk = 0; kk < BK; kk += 16) {
            uint32_t af[4][4], bh[2][4], bl[2][4];
            // A-hi fragments (4 m16 tiles)
#pragma unroll
            for (int i = 0; i < 4; i++)
                ldmx4(af[i], &sAh[wm * 64 + i * 16 + a_r][kk + a_k]);
            // B-hi fragments (4 n8 tiles via 2 x4 loads)
#pragma unroll
            for (int j = 0; j < 2; j++)
                ldmx4(bh[j], &sBh[wn * 32 + j * 16 + b_r][kk + b_k]);
            // B-lo fragments
#pragma unroll
            for (int j = 0; j < 2; j++)
                ldmx4(bl[j], &sBl[wn * 32 + j * 16 + b_r][kk + b_k]);

            // pass 1: ah * bh
#pragma unroll
            for (int i = 0; i < 4; i++)
#pragma unroll
                for (int j = 0; j < 4; j++)
                    mma16816(acc[i][j], af[i], &bh[j >> 1][(j & 1) * 2]);
            // pass 2: ah * bl
#pragma unroll
            for (int i = 0; i < 4; i++)
#pragma unroll
                for (int j = 0; j < 4; j++)
                    mma16816(acc[i][j], af[i], &bl[j >> 1][(j & 1) * 2]);
            // reload af <- A-lo, pass 3: al * bh
#pragma unroll
            for (int i = 0; i < 4; i++)
                ldmx4(af[i], &sAl[wm * 64 + i * 16 + a_r][kk + a_k]);
#pragma unroll
            for (int i = 0; i < 4; i++)
#pragma unroll
                for (int j = 0; j < 4; j++)
                    mma16816(acc[i][j], af[i], &bh[j >> 1][(j & 1) * 2]);
        }
        __syncthreads();
    }

    // ---- epilogue: c-frag rows t/4 (+8), cols (t%4)*2 ----
#pragma unroll
    for (int i = 0; i < 4; i++) {
        int gr = row0 + wm * 64 + i * 16 + (lane >> 2);
#pragma unroll
        for (int j = 0; j < 4; j++) {
            int gc = col0 + wn * 32 + j * 8 + (lane & 3) * 2;
            float bx = bias[gc], by = bias[gc + 1];
            float2 o0 = make_float2(acc[i][j][0] + bx, acc[i][j][1] + by);
            float2 o1 = make_float2(acc[i][j][2] + bx, acc[i][j][3] + by);
            *(float2*)&C[(size_t)gr * N + gc]       = o0;
            *(float2*)&C[(size_t)(gr + 8) * N + gc] = o1;
        }
    }
}

// ---------------- causal GQA flash attention (unchanged) ----------------
#define STR 68

__global__ __launch_bounds__(256, 3)
void attn_kernel(const float* __restrict__ Qp, const float* __restrict__ Kp,
                 const float* __restrict__ Vp, float* __restrict__ Ao)
{
    extern __shared__ float sm[];
    float* sQ  = sm;
    float* sKT = sQ  + 64 * STR;
    float* sV  = sKT + 64 * STR;
    float* sP  = sV  + 64 * STR;

    const int bh = blockIdx.y;
    const int b  = bh >> 5;
    const int h  = bh & 31;
    const int kh = h >> 2;
    const int y  = blockIdx.x;
    const int tid = threadIdx.x;
    const int tx = tid & 15, ty = tid >> 4;

    const float* qbase = Qp + ((size_t)(b * SS + y * 64)) * DD + h * HD;
    const float* kbase = Kp + ((size_t)(b * SS)) * (KH * HD) + kh * HD;
    const float* vbase = Vp + ((size_t)(b * SS)) * (KH * HD) + kh * HD;

    for (int f = tid; f < 1024; f += 256) {
        int r = f >> 4, c4 = (f & 15) * 4;
        float4 v = *(const float4*)&qbase[(size_t)r * DD + c4];
        v.x *= 0.125f; v.y *= 0.125f; v.z *= 0.125f; v.w *= 0.125f;
        *(float4*)&sQ[r * STR + c4] = v;
    }

    float acc[4][4];
#pragma unroll
    for (int i = 0; i < 4; i++)
#pragma unroll
        for (int j = 0; j < 4; j++) acc[i][j] = 0.f;
    float m_r[4], l_r[4];
#pragma unroll
    for (int i = 0; i < 4; i++) { m_r[i] = -1e30f; l_r[i] = 0.f; }

    for (int j = 0; j <= y; j++) {
        for (int f = tid; f < 1024; f += 256) {
            int r = f >> 4, c4 = (f & 15) * 4;
            float4 kv4 = *(const float4*)&kbase[(size_t)(j * 64 + r) * (KH * HD) + c4];
            sKT[(c4 + 0) * STR + r] = kv4.x;
            sKT[(c4 + 1) * STR + r] = kv4.y;
            sKT[(c4 + 2) * STR + r] = kv4.z;
            sKT[(c4 + 3) * STR + r] = kv4.w;
            float4 vv4 = *(const float4*)&vbase[(size_t)(j * 64 + r) * (KH * HD) + c4];
            *(float4*)&sV[r * STR + c4] = vv4;
        }
        __syncthreads();

        float s[4][4];
#pragma unroll
        for (int i = 0; i < 4; i++)
#pragma unroll
            for (int jj = 0; jj < 4; jj++) s[i][jj] = 0.f;
#pragma unroll 8
        for (int d = 0; d < 64; d++) {
            float4 k4 = *(float4*)&sKT[d * STR + tx * 4];
#pragma unroll
            for (int i = 0; i < 4; i++) {
                float qv = sQ[(ty * 4 + i) * STR + d];
                s[i][0] += qv * k4.x; s[i][1] += qv * k4.y;
                s[i][2] += qv * k4.z; s[i][3] += qv * k4.w;
            }
        }

        if (j == y) {
#pragma unroll
            for (int i = 0; i < 4; i++)
#pragma unroll
                for (int jj = 0; jj < 4; jj++)
                    if (tx * 4 + jj > ty * 4 + i) s[i][jj] = -1e30f;
        }

#pragma unroll
        for (int i = 0; i < 4; i++) {
            float rmax = fmaxf(fmaxf(s[i][0], s[i][1]), fmaxf(s[i][2], s[i][3]));
#pragma unroll
            for (int o = 8; o >= 1; o >>= 1)
                rmax = fmaxf(rmax, __shfl_xor_sync(0xffffffffu, rmax, o));
            float mn    = fmaxf(m_r[i], rmax);
            float alpha = __expf(m_r[i] - mn);
            m_r[i] = mn;
            float rs = 0.f;
#pragma unroll
            for (int jj = 0; jj < 4; jj++) {
                float p = __expf(s[i][jj] - mn);
                sP[(ty * 4 + i) * STR + tx * 4 + jj] = p;
                rs += p;
            }
#pragma unroll
            for (int o = 8; o >= 1; o >>= 1)
                rs += __shfl_xor_sync(0xffffffffu, rs, o);
            l_r[i] = l_r[i] * alpha + rs;
#pragma unroll
            for (int jj = 0; jj < 4; jj++) acc[i][jj] *= alpha;
        }
        __syncthreads();

#pragma unroll 8
        for (int k = 0; k < 64; k++) {
            float4 vv = *(float4*)&sV[k * STR + tx * 4];
#pragma unroll
            for (int i = 0; i < 4; i++) {
                float pv = sP[(ty * 4 + i) * STR + k];
                acc[i][0] += pv * vv.x; acc[i][1] += pv * vv.y;
                acc[i][2] += pv * vv.z; acc[i][3] += pv * vv.w;
            }
        }
        __syncthreads();
    }

#pragma unroll
    for (int i = 0; i < 4; i++) {
        int qg = y * 64 + ty * 4 + i;
        float inv = 1.f / l_r[i];
        float4 o = make_float4(acc[i][0] * inv, acc[i][1] * inv,
                               acc[i][2] * inv, acc[i][3] * inv);
        *(float4*)&Ao[((size_t)(b * SS + qg)) * DD + h * HD + tx * 4] = o;
    }
}

#define ATTN_SMEM (4 * 64 * STR * sizeof(float))

// ---------------- launcher ----------------
extern "C" void kernel_launch(void* const* d_in, const int* in_sizes, int n_in,
                              void* d_out, int out_size)
{
    const float* q  = (const float*)d_in[0];
    const float* kv = (const float*)d_in[1];
    // d_in[2] = mask (causal, static) -- unused
    const float* Wq = (const float*)d_in[3];
    const float* bq = (const float*)d_in[4];
    const float* Wk = (const float*)d_in[5];
    const float* bk = (const float*)d_in[6];
    const float* Wv = (const float*)d_in[7];
    const float* bv = (const float*)d_in[8];
    const float* Wo = (const float*)d_in[9];
    const float* bo = (const float*)d_in[10];
    float* out = (float*)d_out;

    float *Qp, *Kp, *Vp, *Ao;
    cudaGetSymbolAddress((void**)&Qp, g_Qp);
    cudaGetSymbolAddress((void**)&Kp, g_Kp);
    cudaGetSymbolAddress((void**)&Vp, g_Vp);
    cudaGetSymbolAddress((void**)&Ao, g_Ao);

    cudaFuncSetAttribute(attn_kernel,
                         cudaFuncAttributeMaxDynamicSharedMemorySize, (int)ATTN_SMEM);

    // 1) Q projection: [2048,2048] = q @ Wq
    gemm_tc<<<dim3(DD / BN, MTOT / BM, 1), 256>>>(
        q, Wq, bq, Qp, Wq, bq, Qp, MTOT, DD, DD);

    // 2) K and V projections fused via gridDim.z: [2048,512]
    gemm_tc<<<dim3((KH * HD) / BN, MTOT / BM, 2), 256>>>(
        kv, Wk, bk, Kp, Wv, bv, Vp, MTOT, KH * HD, DD);

    // 3) causal GQA attention -> Ao [2048, 2048]
    attn_kernel<<<dim3(SS / 64, BB * QH), 256, ATTN_SMEM>>>(Qp, Kp, Vp, Ao);

    // 4) output projection: out = Ao @ Wo + bo
    gemm_tc<<<dim3(DD / BN, MTOT / BM, 1), 256>>>(
        Ao, Wo, bo, out, Wo, bo, out, MTOT, DD, DD);
}

// round 6
// speedup vs baseline: 1.8545x; 1.8545x over previous
#include <cuda_runtime.h>
#include <cuda_bf16.h>
#include <cstdint>

// Problem constants
#define BB   2
#define SS   1024
#define DD   2048
#define QH   32
#define KH   8
#define HD   64
#define KVD  (KH*HD)        // 512
#define MTOT (BB*SS)        // 2048

typedef __nv_bfloat16 bf16;
typedef __nv_bfloat162 bf162;

// ---------------- scratch (device globals: allocation-free) ----------------
// alignas(16): cp.async 16B requires 16B-aligned global source addresses.
__device__ alignas(16) bf16 g_qh[MTOT * DD],  g_ql[MTOT * DD];
__device__ alignas(16) bf16 g_kvh[MTOT * DD], g_kvl[MTOT * DD];
__device__ alignas(16) bf16 g_Wqt_h[DD * DD],  g_Wqt_l[DD * DD];     // [n][k]
__device__ alignas(16) bf16 g_Wkt_h[KVD * DD], g_Wkt_l[KVD * DD];
__device__ alignas(16) bf16 g_Wvt_h[KVD * DD], g_Wvt_l[KVD * DD];
__device__ alignas(16) bf16 g_Wot_h[DD * DD],  g_Wot_l[DD * DD];
__device__ alignas(16) float g_Qp[MTOT * DD];
__device__ alignas(16) float g_Kp[MTOT * KVD];
__device__ alignas(16) float g_Vp[MTOT * KVD];
__device__ alignas(16) bf16 g_Aoh[MTOT * DD], g_Aol[MTOT * DD];

__device__ __forceinline__ void split_bf16(float v, bf16& h, bf16& l) {
    h = __float2bfloat16_rn(v);
    l = __float2bfloat16_rn(v - __bfloat162float(h));
}

// ---------------- convert kernels ----------------
__global__ void k_split(const float* __restrict__ in, bf16* __restrict__ hi,
                        bf16* __restrict__ lo, int n)
{
    int i = (blockIdx.x * blockDim.x + threadIdx.x) * 4;
    if (i >= n) return;
    float4 v = *(const float4*)&in[i];
    bf16 h0, l0, h1, l1, h2, l2, h3, l3;
    split_bf16(v.x, h0, l0); split_bf16(v.y, h1, l1);
    split_bf16(v.z, h2, l2); split_bf16(v.w, h3, l3);
    *(bf162*)&hi[i]     = __halves2bfloat162(h0, h1);
    *(bf162*)&hi[i + 2] = __halves2bfloat162(h2, h3);
    *(bf162*)&lo[i]     = __halves2bfloat162(l0, l1);
    *(bf162*)&lo[i + 2] = __halves2bfloat162(l2, l3);
}

// transpose + split: in fp32 [R][C] -> hi/lo bf16 [C][R]
__global__ void k_tsplit(const float* __restrict__ in, bf16* __restrict__ hi,
                         bf16* __restrict__ lo, int R, int C)
{
    __shared__ float t[32][33];
    int r0 = blockIdx.y * 32, c0 = blockIdx.x * 32;
#pragma unroll
    for (int i = 0; i < 4; i++) {
        int r = r0 + threadIdx.y + i * 8;
        t[threadIdx.y + i * 8][threadIdx.x] = in[(size_t)r * C + c0 + threadIdx.x];
    }
    __syncthreads();
#pragma unroll
    for (int i = 0; i < 4; i++) {
        int c = c0 + threadIdx.y + i * 8;     // output row
        float v = t[threadIdx.x][threadIdx.y + i * 8];
        bf16 h, l; split_bf16(v, h, l);
        hi[(size_t)c * R + r0 + threadIdx.x] = h;
        lo[(size_t)c * R + r0 + threadIdx.x] = l;
    }
}

// ============================================================================
// Tensor-core GEMM on pre-split bf16: C = A @ Bt^T + bias (Bt is [N][K]).
// 3-pass: ah*bh + ah*bl + al*bh, fp32 accum. cp.async double-buffered.
// ============================================================================
#define BM 128
#define BN 128
#define BK 32
#define KSTR 40                       // smem k-stride (bf16): 80B rows
#define TILE_BF (BM * KSTR)
#define STAGE_BF (4 * TILE_BF)        // Ah, Al, Bh, Bl
#define GEMM_SMEM (2 * STAGE_BF * 2)  // bytes (2 stages)

__device__ __forceinline__ void cpa16(void* dst, const void* src) {
    uint32_t d = (uint32_t)__cvta_generic_to_shared(dst);
    asm volatile("cp.async.ca.shared.global [%0], [%1], 16;" :: "r"(d), "l"(src));
}
__device__ __forceinline__ void ldmx4(uint32_t* r, const void* p) {
    uint32_t addr = (uint32_t)__cvta_generic_to_shared(p);
    asm volatile("ldmatrix.sync.aligned.m8n8.x4.shared.b16 {%0,%1,%2,%3}, [%4];"
                 : "=r"(r[0]), "=r"(r[1]), "=r"(r[2]), "=r"(r[3]) : "r"(addr));
}
__device__ __forceinline__ void mma16816(float* c, const uint32_t* a, const uint32_t* b) {
    asm volatile("mma.sync.aligned.m16n8k16.row.col.f32.bf16.bf16.f32 "
                 "{%0,%1,%2,%3}, {%4,%5,%6,%7}, {%8,%9}, {%0,%1,%2,%3};"
                 : "+f"(c[0]), "+f"(c[1]), "+f"(c[2]), "+f"(c[3])
                 : "r"(a[0]), "r"(a[1]), "r"(a[2]), "r"(a[3]),
                   "r"(b[0]), "r"(b[1]));
}

// Stage one 128x32 bf16 tile-quad (Ah/Al/Bh/Bl) into smem.
// 512 chunks of 16B per tile-half: chunk c -> row c>>2, elem offset (c&3)*8.
__device__ __forceinline__ void stage_tiles(
    bf16* base, const bf16* Ah, const bf16* Al, const bf16* Bh, const bf16* Bl,
    int row0, int col0, int kt, int K, int tid)
{
    bf16* pAh = base;               bf16* pAl = base + TILE_BF;
    bf16* pBh = base + 2 * TILE_BF; bf16* pBl = base + 3 * TILE_BF;
#pragma unroll
    for (int p = 0; p < 2; p++) {
        int c   = tid + p * 256;
        int r   = c >> 2;           // 0..127
        int off = (c & 3) * 8;      // 0,8,16,24
        const size_t ga = (size_t)(row0 + r) * K + kt + off;
        const size_t gb = (size_t)(col0 + r) * K + kt + off;
        const int so = r * KSTR + off;
        cpa16(pAh + so, Ah + ga);
        cpa16(pAl + so, Al + ga);
        cpa16(pBh + so, Bh + gb);
        cpa16(pBl + so, Bl + gb);
    }
}

__global__ __launch_bounds__(256, 2)
void gemm_tc(const bf16* __restrict__ Ah, const bf16* __restrict__ Al,
             const bf16* __restrict__ B0h, const bf16* __restrict__ B0l,
             const float* __restrict__ b0, float* __restrict__ C0,
             const bf16* __restrict__ B1h, const bf16* __restrict__ B1l,
             const float* __restrict__ b1, float* __restrict__ C1,
             int M, int N, int K)
{
    const bf16* Bh   = blockIdx.z ? B1h : B0h;
    const bf16* Bl   = blockIdx.z ? B1l : B0l;
    const float* bias = blockIdx.z ? b1 : b0;
    float*       C    = blockIdx.z ? C1 : C0;

    extern __shared__ bf16 smem[];

    const int tid  = threadIdx.x;
    const int lane = tid & 31;
    const int wid  = tid >> 5;
    const int wm   = wid & 1;
    const int wn   = wid >> 1;
    const int row0 = blockIdx.y * BM;
    const int col0 = blockIdx.x * BN;

    float acc[4][4][4];
#pragma unroll
    for (int i = 0; i < 4; i++)
#pragma unroll
        for (int j = 0; j < 4; j++)
#pragma unroll
            for (int k = 0; k < 4; k++) acc[i][j][k] = 0.f;

    const int a_r = lane & 15;
    const int a_k = (lane >> 4) << 3;
    const int b_r = (lane & 7) | ((lane & 16) >> 1);
    const int b_k = lane & 8;

    const int nt = K / BK;

    // ---- prologue: stage tile 0 ----
    stage_tiles(smem, Ah, Al, Bh, Bl, row0, col0, 0, K, tid);
    asm volatile("cp.async.commit_group;");

    for (int t = 0; t < nt; t++) {
        if (t + 1 < nt)
            stage_tiles(smem + ((t + 1) & 1) * STAGE_BF,
                        Ah, Al, Bh, Bl, row0, col0, (t + 1) * BK, K, tid);
        asm volatile("cp.async.commit_group;");
        asm volatile("cp.async.wait_group 1;");
        __syncthreads();

        bf16* base = smem + (t & 1) * STAGE_BF;
        bf16* pAh = base;             bf16* pAl = base + TILE_BF;
        bf16* pBh = base + 2*TILE_BF; bf16* pBl = base + 3*TILE_BF;

#pragma unroll
        for (int kk = 0; kk < BK; kk += 16) {
            uint32_t af[4][4], bh[2][4], bl[2][4];
#pragma unroll
            for (int i = 0; i < 4; i++)
                ldmx4(af[i], pAh + (wm * 64 + i * 16 + a_r) * KSTR + kk + a_k);
#pragma unroll
            for (int j = 0; j < 2; j++)
                ldmx4(bh[j], pBh + (wn * 32 + j * 16 + b_r) * KSTR + kk + b_k);
#pragma unroll
            for (int j = 0; j < 2; j++)
                ldmx4(bl[j], pBl + (wn * 32 + j * 16 + b_r) * KSTR + kk + b_k);

#pragma unroll
            for (int i = 0; i < 4; i++)
#pragma unroll
                for (int j = 0; j < 4; j++)
                    mma16816(acc[i][j], af[i], &bh[j >> 1][(j & 1) * 2]);
#pragma unroll
            for (int i = 0; i < 4; i++)
#pragma unroll
                for (int j = 0; j < 4; j++)
                    mma16816(acc[i][j], af[i], &bl[j >> 1][(j & 1) * 2]);
#pragma unroll
            for (int i = 0; i < 4; i++)
                ldmx4(af[i], pAl + (wm * 64 + i * 16 + a_r) * KSTR + kk + a_k);
#pragma unroll
            for (int i = 0; i < 4; i++)
#pragma unroll
                for (int j = 0; j < 4; j++)
                    mma16816(acc[i][j], af[i], &bh[j >> 1][(j & 1) * 2]);
        }
        __syncthreads();
    }

    // epilogue
#pragma unroll
    for (int i = 0; i < 4; i++) {
        int gr = row0 + wm * 64 + i * 16 + (lane >> 2);
#pragma unroll
        for (int j = 0; j < 4; j++) {
            int gc = col0 + wn * 32 + j * 8 + (lane & 3) * 2;
            float bx = bias[gc], by = bias[gc + 1];
            float2 o0 = make_float2(acc[i][j][0] + bx, acc[i][j][1] + by);
            float2 o1 = make_float2(acc[i][j][2] + bx, acc[i][j][3] + by);
            *(float2*)&C[(size_t)gr * N + gc]       = o0;
            *(float2*)&C[(size_t)(gr + 8) * N + gc] = o1;
        }
    }
}

// ---------------- causal GQA flash attention (epilogue -> bf16 hi/lo) ------
#define STR 68

__global__ __launch_bounds__(256, 3)
void attn_kernel(const float* __restrict__ Qp, const float* __restrict__ Kp,
                 const float* __restrict__ Vp,
                 bf16* __restrict__ Aoh, bf16* __restrict__ Aol)
{
    extern __shared__ float sm[];
    float* sQ  = sm;
    float* sKT = sQ  + 64 * STR;
    float* sV  = sKT + 64 * STR;
    float* sP  = sV  + 64 * STR;

    const int bh = blockIdx.y;
    const int b  = bh >> 5;
    const int h  = bh & 31;
    const int kh = h >> 2;
    const int y  = blockIdx.x;
    const int tid = threadIdx.x;
    const int tx = tid & 15, ty = tid >> 4;

    const float* qbase = Qp + ((size_t)(b * SS + y * 64)) * DD + h * HD;
    const float* kbase = Kp + ((size_t)(b * SS)) * KVD + kh * HD;
    const float* vbase = Vp + ((size_t)(b * SS)) * KVD + kh * HD;

    for (int f = tid; f < 1024; f += 256) {
        int r = f >> 4, c4 = (f & 15) * 4;
        float4 v = *(const float4*)&qbase[(size_t)r * DD + c4];
        v.x *= 0.125f; v.y *= 0.125f; v.z *= 0.125f; v.w *= 0.125f;
        *(float4*)&sQ[r * STR + c4] = v;
    }

    float acc[4][4];
#pragma unroll
    for (int i = 0; i < 4; i++)
#pragma unroll
        for (int j = 0; j < 4; j++) acc[i][j] = 0.f;
    float m_r[4], l_r[4];
#pragma unroll
    for (int i = 0; i < 4; i++) { m_r[i] = -1e30f; l_r[i] = 0.f; }

    for (int j = 0; j <= y; j++) {
        for (int f = tid; f < 1024; f += 256) {
            int r = f >> 4, c4 = (f & 15) * 4;
            float4 kv4 = *(const float4*)&kbase[(size_t)(j * 64 + r) * KVD + c4];
            sKT[(c4 + 0) * STR + r] = kv4.x;
            sKT[(c4 + 1) * STR + r] = kv4.y;
            sKT[(c4 + 2) * STR + r] = kv4.z;
            sKT[(c4 + 3) * STR + r] = kv4.w;
            float4 vv4 = *(const float4*)&vbase[(size_t)(j * 64 + r) * KVD + c4];
            *(float4*)&sV[r * STR + c4] = vv4;
        }
        __syncthreads();

        float s[4][4];
#pragma unroll
        for (int i = 0; i < 4; i++)
#pragma unroll
            for (int jj = 0; jj < 4; jj++) s[i][jj] = 0.f;
#pragma unroll 8
        for (int d = 0; d < 64; d++) {
            float4 k4 = *(float4*)&sKT[d * STR + tx * 4];
#pragma unroll
            for (int i = 0; i < 4; i++) {
                float qv = sQ[(ty * 4 + i) * STR + d];
                s[i][0] += qv * k4.x; s[i][1] += qv * k4.y;
                s[i][2] += qv * k4.z; s[i][3] += qv * k4.w;
            }
        }

        if (j == y) {
#pragma unroll
            for (int i = 0; i < 4; i++)
#pragma unroll
                for (int jj = 0; jj < 4; jj++)
                    if (tx * 4 + jj > ty * 4 + i) s[i][jj] = -1e30f;
        }

#pragma unroll
        for (int i = 0; i < 4; i++) {
            float rmax = fmaxf(fmaxf(s[i][0], s[i][1]), fmaxf(s[i][2], s[i][3]));
#pragma unroll
            for (int o = 8; o >= 1; o >>= 1)
                rmax = fmaxf(rmax, __shfl_xor_sync(0xffffffffu, rmax, o));
            float mn    = fmaxf(m_r[i], rmax);
            float alpha = __expf(m_r[i] - mn);
            m_r[i] = mn;
            float rs = 0.f;
#pragma unroll
            for (int jj = 0; jj < 4; jj++) {
                float p = __expf(s[i][jj] - mn);
                sP[(ty * 4 + i) * STR + tx * 4 + jj] = p;
                rs += p;
            }
#pragma unroll
            for (int o = 8; o >= 1; o >>= 1)
                rs += __shfl_xor_sync(0xffffffffu, rs, o);
            l_r[i] = l_r[i] * alpha + rs;
#pragma unroll
            for (int jj = 0; jj < 4; jj++) acc[i][jj] *= alpha;
        }
        __syncthreads();

#pragma unroll 8
        for (int k = 0; k < 64; k++) {
            float4 vv = *(float4*)&sV[k * STR + tx * 4];
#pragma unroll
            for (int i = 0; i < 4; i++) {
                float pv = sP[(ty * 4 + i) * STR + k];
                acc[i][0] += pv * vv.x; acc[i][1] += pv * vv.y;
                acc[i][2] += pv * vv.z; acc[i][3] += pv * vv.w;
            }
        }
        __syncthreads();
    }

    // normalize + split-write to bf16 hi/lo
#pragma unroll
    for (int i = 0; i < 4; i++) {
        int qg = y * 64 + ty * 4 + i;
        float inv = 1.f / l_r[i];
        float v0 = acc[i][0] * inv, v1 = acc[i][1] * inv;
        float v2 = acc[i][2] * inv, v3 = acc[i][3] * inv;
        bf16 h0, l0, h1, l1, h2, l2, h3, l3;
        split_bf16(v0, h0, l0); split_bf16(v1, h1, l1);
        split_bf16(v2, h2, l2); split_bf16(v3, h3, l3);
        size_t base = ((size_t)(b * SS + qg)) * DD + h * HD + tx * 4;
        *(bf162*)&Aoh[base]     = __halves2bfloat162(h0, h1);
        *(bf162*)&Aoh[base + 2] = __halves2bfloat162(h2, h3);
        *(bf162*)&Aol[base]     = __halves2bfloat162(l0, l1);
        *(bf162*)&Aol[base + 2] = __halves2bfloat162(l2, l3);
    }
}

#define ATTN_SMEM (4 * 64 * STR * sizeof(float))

// ---------------- launcher ----------------
extern "C" void kernel_launch(void* const* d_in, const int* in_sizes, int n_in,
                              void* d_out, int out_size)
{
    const float* q  = (const float*)d_in[0];
    const float* kv = (const float*)d_in[1];
    // d_in[2] = mask (causal, static) -- unused
    const float* Wq = (const float*)d_in[3];
    const float* bq = (const float*)d_in[4];
    const float* Wk = (const float*)d_in[5];
    const float* bk = (const float*)d_in[6];
    const float* Wv = (const float*)d_in[7];
    const float* bv = (const float*)d_in[8];
    const float* Wo = (const float*)d_in[9];
    const float* bo = (const float*)d_in[10];
    float* out = (float*)d_out;

    bf16 *qh, *ql, *kvh, *kvl, *Wqth, *Wqtl, *Wkth, *Wktl, *Wvth, *Wvtl, *Woth, *Wotl;
    bf16 *Aoh, *Aol;
    float *Qp, *Kp, *Vp;
    cudaGetSymbolAddress((void**)&qh,  g_qh);   cudaGetSymbolAddress((void**)&ql,  g_ql);
    cudaGetSymbolAddress((void**)&kvh, g_kvh);  cudaGetSymbolAddress((void**)&kvl, g_kvl);
    cudaGetSymbolAddress((void**)&Wqth, g_Wqt_h); cudaGetSymbolAddress((void**)&Wqtl, g_Wqt_l);
    cudaGetSymbolAddress((void**)&Wkth, g_Wkt_h); cudaGetSymbolAddress((void**)&Wktl, g_Wkt_l);
    cudaGetSymbolAddress((void**)&Wvth, g_Wvt_h); cudaGetSymbolAddress((void**)&Wvtl, g_Wvt_l);
    cudaGetSymbolAddress((void**)&Woth, g_Wot_h); cudaGetSymbolAddress((void**)&Wotl, g_Wot_l);
    cudaGetSymbolAddress((void**)&Qp, g_Qp);
    cudaGetSymbolAddress((void**)&Kp, g_Kp);
    cudaGetSymbolAddress((void**)&Vp, g_Vp);
    cudaGetSymbolAddress((void**)&Aoh, g_Aoh);  cudaGetSymbolAddress((void**)&Aol, g_Aol);

    cudaFuncSetAttribute(attn_kernel,
                         cudaFuncAttributeMaxDynamicSharedMemorySize, (int)ATTN_SMEM);
    cudaFuncSetAttribute(gemm_tc,
                         cudaFuncAttributeMaxDynamicSharedMemorySize, GEMM_SMEM);

    // ---- converts ----
    k_split<<<(MTOT * DD / 4 + 255) / 256, 256>>>(q,  qh,  ql,  MTOT * DD);
    k_split<<<(MTOT * DD / 4 + 255) / 256, 256>>>(kv, kvh, kvl, MTOT * DD);
    k_tsplit<<<dim3(DD / 32,  DD / 32), dim3(32, 8)>>>(Wq, Wqth, Wqtl, DD, DD);
    k_tsplit<<<dim3(KVD / 32, DD / 32), dim3(32, 8)>>>(Wk, Wkth, Wktl, DD, KVD);
    k_tsplit<<<dim3(KVD / 32, DD / 32), dim3(32, 8)>>>(Wv, Wvth, Wvtl, DD, KVD);
    k_tsplit<<<dim3(DD / 32,  DD / 32), dim3(32, 8)>>>(Wo, Woth, Wotl, DD, DD);

    // ---- Q projection ----
    gemm_tc<<<dim3(DD / BN, MTOT / BM, 1), 256, GEMM_SMEM>>>(
        qh, ql, Wqth, Wqtl, bq, Qp, Wqth, Wqtl, bq, Qp, MTOT, DD, DD);

    // ---- K and V projections (fused via z) ----
    gemm_tc<<<dim3(KVD / BN, MTOT / BM, 2), 256, GEMM_SMEM>>>(
        kvh, kvl, Wkth, Wktl, bk, Kp, Wvth, Wvtl, bv, Vp, MTOT, KVD, DD);

    // ---- attention -> Ao (bf16 hi/lo) ----
    attn_kernel<<<dim3(SS / 64, BB * QH), 256, ATTN_SMEM>>>(Qp, Kp, Vp, Aoh, Aol);

    // ---- output projection ----
    gemm_tc<<<dim3(DD / BN, MTOT / BM, 1), 256, GEMM_SMEM>>>(
        Aoh, Aol, Woth, Wotl, bo, out, Woth, Wotl, bo, out, MTOT, DD, DD);
}

// round 8
// speedup vs baseline: 2.5335x; 1.3661x over previous
#include <cuda_runtime.h>
#include <cuda_bf16.h>
#include <cstdint>

// Problem constants
#define BB   2
#define SS   1024
#define DD   2048
#define QH   32
#define KH   8
#define HD   64
#define KVD  (KH*HD)        // 512
#define MTOT (BB*SS)        // 2048

typedef __nv_bfloat16 bf16;
typedef __nv_bfloat162 bf162;

// ---------------- scratch (device globals; alignas(16) for cp.async) -------
__device__ alignas(16) bf16 g_qh[MTOT * DD],  g_ql[MTOT * DD];
__device__ alignas(16) bf16 g_kvh[MTOT * DD], g_kvl[MTOT * DD];
__device__ alignas(16) bf16 g_Wqt_h[DD * DD],  g_Wqt_l[DD * DD];     // [n][k]
__device__ alignas(16) bf16 g_Wkt_h[KVD * DD], g_Wkt_l[KVD * DD];
__device__ alignas(16) bf16 g_Wvt_h[KVD * DD], g_Wvt_l[KVD * DD];
__device__ alignas(16) bf16 g_Wot_h[DD * DD],  g_Wot_l[DD * DD];
__device__ alignas(16) bf16 g_Qsh[MTOT * DD],  g_Qsl[MTOT * DD];     // Q proj split
__device__ alignas(16) bf16 g_Ksh[MTOT * KVD], g_Ksl[MTOT * KVD];    // K proj split
__device__ alignas(16) bf16 g_Vth[BB * KVD * SS], g_Vtl[BB * KVD * SS]; // V^T [b*512+d][s]
__device__ alignas(16) bf16 g_Aoh[MTOT * DD], g_Aol[MTOT * DD];

__device__ __forceinline__ void split_bf16(float v, bf16& h, bf16& l) {
    h = __float2bfloat16_rn(v);
    l = __float2bfloat16_rn(v - __bfloat162float(h));
}
__device__ __forceinline__ uint32_t pack2(bf16 a, bf16 b) {
    bf162 t = __halves2bfloat162(a, b);
    return *(uint32_t*)&t;
}

// ---------------- convert kernels ----------------
__global__ void k_split(const float* __restrict__ in, bf16* __restrict__ hi,
                        bf16* __restrict__ lo, int n)
{
    int i = (blockIdx.x * blockDim.x + threadIdx.x) * 4;
    if (i >= n) return;
    float4 v = *(const float4*)&in[i];
    bf16 h0, l0, h1, l1, h2, l2, h3, l3;
    split_bf16(v.x, h0, l0); split_bf16(v.y, h1, l1);
    split_bf16(v.z, h2, l2); split_bf16(v.w, h3, l3);
    *(bf162*)&hi[i]     = __halves2bfloat162(h0, h1);
    *(bf162*)&hi[i + 2] = __halves2bfloat162(h2, h3);
    *(bf162*)&lo[i]     = __halves2bfloat162(l0, l1);
    *(bf162*)&lo[i + 2] = __halves2bfloat162(l2, l3);
}

__global__ void k_tsplit(const float* __restrict__ in, bf16* __restrict__ hi,
                         bf16* __restrict__ lo, int R, int C)
{
    __shared__ float t[32][33];
    int r0 = blockIdx.y * 32, c0 = blockIdx.x * 32;
#pragma unroll
    for (int i = 0; i < 4; i++) {
        int r = r0 + threadIdx.y + i * 8;
        t[threadIdx.y + i * 8][threadIdx.x] = in[(size_t)r * C + c0 + threadIdx.x];
    }
    __syncthreads();
#pragma unroll
    for (int i = 0; i < 4; i++) {
        int c = c0 + threadIdx.y + i * 8;
        float v = t[threadIdx.x][threadIdx.y + i * 8];
        bf16 h, l; split_bf16(v, h, l);
        hi[(size_t)c * R + r0 + threadIdx.x] = h;
        lo[(size_t)c * R + r0 + threadIdx.x] = l;
    }
}

// ============================================================================
// Tensor-core GEMM on pre-split bf16. Epilogue modes:
//   0: fp32 C      1: split bf16 natural Ch/Cl      2: split bf16 V-transposed
// ============================================================================
#define BM 128
#define BN 128
#define BK 32
#define KSTR 40
#define TILE_BF (BM * KSTR)
#define STAGE_BF (4 * TILE_BF)
#define GEMM_SMEM (2 * STAGE_BF * 2)

__device__ __forceinline__ void cpa16(void* dst, const void* src) {
    uint32_t d = (uint32_t)__cvta_generic_to_shared(dst);
    asm volatile("cp.async.ca.shared.global [%0], [%1], 16;" :: "r"(d), "l"(src));
}
__device__ __forceinline__ void ldmx4(uint32_t* r, const void* p) {
    uint32_t addr = (uint32_t)__cvta_generic_to_shared(p);
    asm volatile("ldmatrix.sync.aligned.m8n8.x4.shared.b16 {%0,%1,%2,%3}, [%4];"
                 : "=r"(r[0]), "=r"(r[1]), "=r"(r[2]), "=r"(r[3]) : "r"(addr));
}
__device__ __forceinline__ void mma16816(float* c, const uint32_t* a, const uint32_t* b) {
    asm volatile("mma.sync.aligned.m16n8k16.row.col.f32.bf16.bf16.f32 "
                 "{%0,%1,%2,%3}, {%4,%5,%6,%7}, {%8,%9}, {%0,%1,%2,%3};"
                 : "+f"(c[0]), "+f"(c[1]), "+f"(c[2]), "+f"(c[3])
                 : "r"(a[0]), "r"(a[1]), "r"(a[2]), "r"(a[3]),
                   "r"(b[0]), "r"(b[1]));
}

__device__ __forceinline__ void stage_tiles(
    bf16* base, const bf16* Ah, const bf16* Al, const bf16* Bh, const bf16* Bl,
    int row0, int col0, int kt, int K, int tid)
{
    bf16* pAh = base;               bf16* pAl = base + TILE_BF;
    bf16* pBh = base + 2 * TILE_BF; bf16* pBl = base + 3 * TILE_BF;
#pragma unroll
    for (int p = 0; p < 2; p++) {
        int c   = tid + p * 256;
        int r   = c >> 2;
        int off = (c & 3) * 8;
        const size_t ga = (size_t)(row0 + r) * K + kt + off;
        const size_t gb = (size_t)(col0 + r) * K + kt + off;
        const int so = r * KSTR + off;
        cpa16(pAh + so, Ah + ga);
        cpa16(pAl + so, Al + ga);
        cpa16(pBh + so, Bh + gb);
        cpa16(pBl + so, Bl + gb);
    }
}

__global__ __launch_bounds__(256, 2)
void gemm_tc(const bf16* __restrict__ Ah, const bf16* __restrict__ Al,
             const bf16* __restrict__ B0h, const bf16* __restrict__ B0l,
             const float* __restrict__ b0, float* __restrict__ C0,
             bf16* __restrict__ C0h, bf16* __restrict__ C0l, int mode0,
             const bf16* __restrict__ B1h, const bf16* __restrict__ B1l,
             const float* __restrict__ b1, float* __restrict__ C1,
             bf16* __restrict__ C1h, bf16* __restrict__ C1l, int mode1,
             int M, int N, int K)
{
    const bf16* Bh   = blockIdx.z ? B1h : B0h;
    const bf16* Bl   = blockIdx.z ? B1l : B0l;
    const float* bias = blockIdx.z ? b1 : b0;
    float* C   = blockIdx.z ? C1 : C0;
    bf16*  Ch  = blockIdx.z ? C1h : C0h;
    bf16*  Cl  = blockIdx.z ? C1l : C0l;
    const int mode = blockIdx.z ? mode1 : mode0;

    extern __shared__ bf16 smem[];

    const int tid  = threadIdx.x;
    const int lane = tid & 31;
    const int wid  = tid >> 5;
    const int wm   = wid & 1;
    const int wn   = wid >> 1;
    const int row0 = blockIdx.y * BM;
    const int col0 = blockIdx.x * BN;

    float acc[4][4][4];
#pragma unroll
    for (int i = 0; i < 4; i++)
#pragma unroll
        for (int j = 0; j < 4; j++)
#pragma unroll
            for (int k = 0; k < 4; k++) acc[i][j][k] = 0.f;

    const int a_r = lane & 15;
    const int a_k = (lane >> 4) << 3;
    const int b_r = (lane & 7) | ((lane & 16) >> 1);
    const int b_k = lane & 8;

    const int nt = K / BK;

    stage_tiles(smem, Ah, Al, Bh, Bl, row0, col0, 0, K, tid);
    asm volatile("cp.async.commit_group;");

    for (int t = 0; t < nt; t++) {
        if (t + 1 < nt)
            stage_tiles(smem + ((t + 1) & 1) * STAGE_BF,
                        Ah, Al, Bh, Bl, row0, col0, (t + 1) * BK, K, tid);
        asm volatile("cp.async.commit_group;");
        asm volatile("cp.async.wait_group 1;");
        __syncthreads();

        bf16* base = smem + (t & 1) * STAGE_BF;
        bf16* pAh = base;             bf16* pAl = base + TILE_BF;
        bf16* pBh = base + 2*TILE_BF; bf16* pBl = base + 3*TILE_BF;

#pragma unroll
        for (int kk = 0; kk < BK; kk += 16) {
            uint32_t af[4][4], bh[2][4], bl[2][4];
#pragma unroll
            for (int i = 0; i < 4; i++)
                ldmx4(af[i], pAh + (wm * 64 + i * 16 + a_r) * KSTR + kk + a_k);
#pragma unroll
            for (int j = 0; j < 2; j++)
                ldmx4(bh[j], pBh + (wn * 32 + j * 16 + b_r) * KSTR + kk + b_k);
#pragma unroll
            for (int j = 0; j < 2; j++)
                ldmx4(bl[j], pBl + (wn * 32 + j * 16 + b_r) * KSTR + kk + b_k);

#pragma unroll
            for (int i = 0; i < 4; i++)
#pragma unroll
                for (int j = 0; j < 4; j++)
                    mma16816(acc[i][j], af[i], &bh[j >> 1][(j & 1) * 2]);
#pragma unroll
            for (int i = 0; i < 4; i++)
#pragma unroll
                for (int j = 0; j < 4; j++)
                    mma16816(acc[i][j], af[i], &bl[j >> 1][(j & 1) * 2]);
#pragma unroll
            for (int i = 0; i < 4; i++)
                ldmx4(af[i], pAl + (wm * 64 + i * 16 + a_r) * KSTR + kk + a_k);
#pragma unroll
            for (int i = 0; i < 4; i++)
#pragma unroll
                for (int j = 0; j < 4; j++)
                    mma16816(acc[i][j], af[i], &bh[j >> 1][(j & 1) * 2]);
        }
        __syncthreads();
    }

    // epilogue
#pragma unroll
    for (int i = 0; i < 4; i++) {
        int gr = row0 + wm * 64 + i * 16 + (lane >> 2);
#pragma unroll
        for (int j = 0; j < 4; j++) {
            int gc = col0 + wn * 32 + j * 8 + (lane & 3) * 2;
            float bx = bias[gc], by = bias[gc + 1];
            float v0 = acc[i][j][0] + bx, v1 = acc[i][j][1] + by;
            float v2 = acc[i][j][2] + bx, v3 = acc[i][j][3] + by;
            if (mode == 0) {
                *(float2*)&C[(size_t)gr * N + gc]       = make_float2(v0, v1);
                *(float2*)&C[(size_t)(gr + 8) * N + gc] = make_float2(v2, v3);
            } else if (mode == 1) {
                bf16 h0,l0,h1,l1,h2,l2,h3,l3;
                split_bf16(v0,h0,l0); split_bf16(v1,h1,l1);
                split_bf16(v2,h2,l2); split_bf16(v3,h3,l3);
                *(uint32_t*)&Ch[(size_t)gr * N + gc]       = pack2(h0, h1);
                *(uint32_t*)&Cl[(size_t)gr * N + gc]       = pack2(l0, l1);
                *(uint32_t*)&Ch[(size_t)(gr + 8) * N + gc] = pack2(h2, h3);
                *(uint32_t*)&Cl[(size_t)(gr + 8) * N + gc] = pack2(l2, l3);
            } else {
                // V-transposed: Vt[(b*KVD + gc)][s], b = gr>>10, s = gr&1023
                int b0i = gr >> 10, s0 = gr & 1023;
                int b1i = (gr + 8) >> 10, s1 = (gr + 8) & 1023;
                bf16 h, l;
                size_t i00 = ((size_t)b0i * KVD + gc) * SS + s0;
                size_t i01 = ((size_t)b0i * KVD + gc + 1) * SS + s0;
                size_t i10 = ((size_t)b1i * KVD + gc) * SS + s1;
                size_t i11 = ((size_t)b1i * KVD + gc + 1) * SS + s1;
                split_bf16(v0, h, l); Ch[i00] = h; Cl[i00] = l;
                split_bf16(v1, h, l); Ch[i01] = h; Cl[i01] = l;
                split_bf16(v2, h, l); Ch[i10] = h; Cl[i10] = l;
                split_bf16(v3, h, l); Ch[i11] = h; Cl[i11] = l;
            }
        }
    }
}

// ============================================================================
// Tensor-core causal GQA flash attention.
// Block: 128 q-rows x one (b,h). 8 warps, m-split (16 rows each, full N).
// S = Q K^T (3-term split), online softmax, O += P V (3-term split).
// ============================================================================
#define QSTR 72                          // smem row stride (bf16): 144 B
#define ATTN_SMEM (2 * 128 * QSTR * 2)   // 36864 B

__global__ __launch_bounds__(256)
void attn_mma(const bf16* __restrict__ Qh, const bf16* __restrict__ Ql,
              const bf16* __restrict__ Kh, const bf16* __restrict__ Kl,
              const bf16* __restrict__ Vth, const bf16* __restrict__ Vtl,
              bf16* __restrict__ Aoh, bf16* __restrict__ Aol)
{
    extern __shared__ bf16 sm[];
    bf16* sQh = sm;                      // [128][QSTR]
    bf16* sQl = sm + 128 * QSTR;
    // overlay (after Q consumed):
    bf16* sKh = sm;                      // [64][QSTR]
    bf16* sKl = sm + 64 * QSTR;
    bf16* sVh = sm + 128 * QSTR;         // Vt [64 d][QSTR]
    bf16* sVl = sm + 192 * QSTR;

    const int tid = threadIdx.x, lane = tid & 31, wid = tid >> 5;
    const int y  = blockIdx.x;           // q tile 0..7
    const int bh = blockIdx.y;
    const int b  = bh >> 5, h = bh & 31, kh = h >> 2;
    const int qtok0 = b * SS + y * 128;

    const int a_r = lane & 15;
    const int a_k = (lane >> 4) << 3;
    const int b_r = (lane & 7) | ((lane & 16) >> 1);
    const int b_k = lane & 8;

    // ---- stage Q tile (128 rows x 64 d, hi+lo) ----
#pragma unroll
    for (int p = 0; p < 4; p++) {
        int c = tid + p * 256;           // 0..1023
        int r = c >> 3, off = (c & 7) * 8;
        const size_t g = (size_t)(qtok0 + r) * DD + h * HD + off;
        cpa16(sQh + r * QSTR + off, Qh + g);
        cpa16(sQl + r * QSTR + off, Ql + g);
    }
    asm volatile("cp.async.commit_group;");
    asm volatile("cp.async.wait_group 0;");
    __syncthreads();

    // Q a-frags to registers (4 k-chunks of 16)
    uint32_t qah[4][4], qal[4][4];
#pragma unroll
    for (int kk = 0; kk < 4; kk++) {
        ldmx4(qah[kk], sQh + (wid * 16 + a_r) * QSTR + kk * 16 + a_k);
        ldmx4(qal[kk], sQl + (wid * 16 + a_r) * QSTR + kk * 16 + a_k);
    }
    __syncthreads();   // Q smem region now free for K/V

    float oacc[8][4];
#pragma unroll
    for (int f = 0; f < 8; f++)
#pragma unroll
        for (int e = 0; e < 4; e++) oacc[f][e] = 0.f;
    float mA = -1e30f, mB = -1e30f, lA = 0.f, lB = 0.f;

    const int qrowA = y * 128 + wid * 16 + (lane >> 2);   // seq idx, rows e0/e1
    const int jend = 2 * y + 1;

    for (int j = 0; j <= jend; j++) {
        // ---- stage K [64 kc][64 d] and Vt [64 d][64 kc] ----
        const int ktok0 = b * SS + j * 64;
#pragma unroll
        for (int p = 0; p < 2; p++) {
            int c = tid + p * 256;       // 0..511
            int r = c >> 3, off = (c & 7) * 8;
            const size_t gk = (size_t)(ktok0 + r) * KVD + kh * HD + off;
            cpa16(sKh + r * QSTR + off, Kh + gk);
            cpa16(sKl + r * QSTR + off, Kl + gk);
            const size_t gv = ((size_t)b * KVD + kh * HD + r) * SS + j * 64 + off;
            cpa16(sVh + r * QSTR + off, Vth + gv);
            cpa16(sVl + r * QSTR + off, Vtl + gv);
        }
        asm volatile("cp.async.commit_group;");
        asm volatile("cp.async.wait_group 0;");
        __syncthreads();

        if (j * 64 <= y * 128 + wid * 16 + 15) {   // warp has unmasked cols
            // ---- S = Q K^T, 3-term split ----
            float sacc[8][4];
#pragma unroll
            for (int f = 0; f < 8; f++)
#pragma unroll
                for (int e = 0; e < 4; e++) sacc[f][e] = 0.f;

            uint32_t kb[4][4];
#pragma unroll
            for (int kk = 0; kk < 4; kk++) {
#pragma unroll
                for (int nb = 0; nb < 4; nb++)
                    ldmx4(kb[nb], sKh + (nb * 16 + b_r) * QSTR + kk * 16 + b_k);
#pragma unroll
                for (int f = 0; f < 8; f++)
                    mma16816(sacc[f], qah[kk], &kb[f >> 1][(f & 1) * 2]);
#pragma unroll
                for (int f = 0; f < 8; f++)
                    mma16816(sacc[f], qal[kk], &kb[f >> 1][(f & 1) * 2]);
#pragma unroll
                for (int nb = 0; nb < 4; nb++)
                    ldmx4(kb[nb], sKl + (nb * 16 + b_r) * QSTR + kk * 16 + b_k);
#pragma unroll
                for (int f = 0; f < 8; f++)
                    mma16816(sacc[f], qah[kk], &kb[f >> 1][(f & 1) * 2]);
            }

            // ---- scale + causal mask ----
            const bool diag = (j >= 2 * y);
#pragma unroll
            for (int f = 0; f < 8; f++)
#pragma unroll
                for (int e = 0; e < 4; e++) {
                    float v = sacc[f][e] * 0.125f;
                    if (diag) {
                        int kg = j * 64 + f * 8 + (lane & 3) * 2 + (e & 1);
                        int qg = qrowA + (e >> 1) * 8;
                        if (kg > qg) v = -1e30f;
                    }
                    sacc[f][e] = v;
                }

            // ---- online softmax (rows A: e0/e1, rows B: e2/e3) ----
            float tmA = -1e30f, tmB = -1e30f;
#pragma unroll
            for (int f = 0; f < 8; f++) {
                tmA = fmaxf(tmA, fmaxf(sacc[f][0], sacc[f][1]));
                tmB = fmaxf(tmB, fmaxf(sacc[f][2], sacc[f][3]));
            }
            tmA = fmaxf(tmA, __shfl_xor_sync(0xffffffffu, tmA, 1));
            tmA = fmaxf(tmA, __shfl_xor_sync(0xffffffffu, tmA, 2));
            tmB = fmaxf(tmB, __shfl_xor_sync(0xffffffffu, tmB, 1));
            tmB = fmaxf(tmB, __shfl_xor_sync(0xffffffffu, tmB, 2));
            float mnA = fmaxf(mA, tmA), mnB = fmaxf(mB, tmB);
            float alA = __expf(mA - mnA), alB = __expf(mB - mnB);
            mA = mnA; mB = mnB;

            float suA = 0.f, suB = 0.f;
#pragma unroll
            for (int f = 0; f < 8; f++) {
                float p0 = __expf(sacc[f][0] - mA);
                float p1 = __expf(sacc[f][1] - mA);
                float p2 = __expf(sacc[f][2] - mB);
                float p3 = __expf(sacc[f][3] - mB);
                suA += p0 + p1; suB += p2 + p3;
                sacc[f][0] = p0; sacc[f][1] = p1; sacc[f][2] = p2; sacc[f][3] = p3;
            }
            suA += __shfl_xor_sync(0xffffffffu, suA, 1);
            suA += __shfl_xor_sync(0xffffffffu, suA, 2);
            suB += __shfl_xor_sync(0xffffffffu, suB, 1);
            suB += __shfl_xor_sync(0xffffffffu, suB, 2);
            lA = lA * alA + suA; lB = lB * alB + suB;

#pragma unroll
            for (int f = 0; f < 8; f++) {
                oacc[f][0] *= alA; oacc[f][1] *= alA;
                oacc[f][2] *= alB; oacc[f][3] *= alB;
            }

            // ---- O += P V (per kc-chunk: pack P, MMA with Vt frags) ----
            uint32_t vb[4][4];
#pragma unroll
            for (int c = 0; c < 4; c++) {
                const int f0 = 2 * c, f1 = 2 * c + 1;
                bf16 hh[8], ll[8];
                split_bf16(sacc[f0][0], hh[0], ll[0]);
                split_bf16(sacc[f0][1], hh[1], ll[1]);
                split_bf16(sacc[f0][2], hh[2], ll[2]);
                split_bf16(sacc[f0][3], hh[3], ll[3]);
                split_bf16(sacc[f1][0], hh[4], ll[4]);
                split_bf16(sacc[f1][1], hh[5], ll[5]);
                split_bf16(sacc[f1][2], hh[6], ll[6]);
                split_bf16(sacc[f1][3], hh[7], ll[7]);
                uint32_t pah[4] = { pack2(hh[0], hh[1]), pack2(hh[2], hh[3]),
                                    pack2(hh[4], hh[5]), pack2(hh[6], hh[7]) };
                uint32_t pal[4] = { pack2(ll[0], ll[1]), pack2(ll[2], ll[3]),
                                    pack2(ll[4], ll[5]), pack2(ll[6], ll[7]) };
#pragma unroll
                for (int nb = 0; nb < 4; nb++)
                    ldmx4(vb[nb], sVh + (nb * 16 + b_r) * QSTR + c * 16 + b_k);
#pragma unroll
                for (int f = 0; f < 8; f++)
                    mma16816(oacc[f], pah, &vb[f >> 1][(f & 1) * 2]);
#pragma unroll
                for (int f = 0; f < 8; f++)
                    mma16816(oacc[f], pal, &vb[f >> 1][(f & 1) * 2]);
#pragma unroll
                for (int nb = 0; nb < 4; nb++)
                    ldmx4(vb[nb], sVl + (nb * 16 + b_r) * QSTR + c * 16 + b_k);
#pragma unroll
                for (int f = 0; f < 8; f++)
                    mma16816(oacc[f], pah, &vb[f >> 1][(f & 1) * 2]);
            }
        }
        __syncthreads();   // before next tile staging overwrites K/V
    }

    // ---- normalize + split-write O ----
    const float ivA = 1.f / lA, ivB = 1.f / lB;
    const int tokA = qtok0 + wid * 16 + (lane >> 2);
#pragma unroll
    for (int f = 0; f < 8; f++) {
        int col = h * HD + f * 8 + (lane & 3) * 2;
        bf16 h0,l0,h1,l1,h2,l2,h3,l3;
        split_bf16(oacc[f][0] * ivA, h0, l0);
        split_bf16(oacc[f][1] * ivA, h1, l1);
        split_bf16(oacc[f][2] * ivB, h2, l2);
        split_bf16(oacc[f][3] * ivB, h3, l3);
        *(uint32_t*)&Aoh[(size_t)tokA * DD + col]       = pack2(h0, h1);
        *(uint32_t*)&Aol[(size_t)tokA * DD + col]       = pack2(l0, l1);
        *(uint32_t*)&Aoh[(size_t)(tokA + 8) * DD + col] = pack2(h2, h3);
        *(uint32_t*)&Aol[(size_t)(tokA + 8) * DD + col] = pack2(l2, l3);
    }
}

// ---------------- launcher ----------------
extern "C" void kernel_launch(void* const* d_in, const int* in_sizes, int n_in,
                              void* d_out, int out_size)
{
    const float* q  = (const float*)d_in[0];
    const float* kv = (const float*)d_in[1];
    // d_in[2] = mask (causal, static) -- unused
    const float* Wq = (const float*)d_in[3];
    const float* bq = (const float*)d_in[4];
    const float* Wk = (const float*)d_in[5];
    const float* bk = (const float*)d_in[6];
    const float* Wv = (const float*)d_in[7];
    const float* bv = (const float*)d_in[8];
    const float* Wo = (const float*)d_in[9];
    const float* bo = (const float*)d_in[10];
    float* out = (float*)d_out;

    bf16 *qh, *ql, *kvh, *kvl, *Wqth, *Wqtl, *Wkth, *Wktl, *Wvth_, *Wvtl_, *Woth, *Wotl;
    bf16 *Qsh, *Qsl, *Ksh, *Ksl, *Vth, *Vtl, *Aoh, *Aol;
    cudaGetSymbolAddress((void**)&qh,  g_qh);   cudaGetSymbolAddress((void**)&ql,  g_ql);
    cudaGetSymbolAddress((void**)&kvh, g_kvh);  cudaGetSymbolAddress((void**)&kvl, g_kvl);
    cudaGetSymbolAddress((void**)&Wqth, g_Wqt_h); cudaGetSymbolAddress((void**)&Wqtl, g_Wqt_l);
    cudaGetSymbolAddress((void**)&Wkth, g_Wkt_h); cudaGetSymbolAddress((void**)&Wktl, g_Wkt_l);
    cudaGetSymbolAddress((void**)&Wvth_, g_Wvt_h); cudaGetSymbolAddress((void**)&Wvtl_, g_Wvt_l);
    cudaGetSymbolAddress((void**)&Woth, g_Wot_h); cudaGetSymbolAddress((void**)&Wotl, g_Wot_l);
    cudaGetSymbolAddress((void**)&Qsh, g_Qsh);  cudaGetSymbolAddress((void**)&Qsl, g_Qsl);
    cudaGetSymbolAddress((void**)&Ksh, g_Ksh);  cudaGetSymbolAddress((void**)&Ksl, g_Ksl);
    cudaGetSymbolAddress((void**)&Vth, g_Vth);  cudaGetSymbolAddress((void**)&Vtl, g_Vtl);
    cudaGetSymbolAddress((void**)&Aoh, g_Aoh);  cudaGetSymbolAddress((void**)&Aol, g_Aol);

    cudaFuncSetAttribute(gemm_tc,
                         cudaFuncAttributeMaxDynamicSharedMemorySize, GEMM_SMEM);
    cudaFuncSetAttribute(attn_mma,
                         cudaFuncAttributeMaxDynamicSharedMemorySize, ATTN_SMEM);

    // ---- converts ----
    k_split<<<(MTOT * DD / 4 + 255) / 256, 256>>>(q,  qh,  ql,  MTOT * DD);
    k_split<<<(MTOT * DD / 4 + 255) / 256, 256>>>(kv, kvh, kvl, MTOT * DD);
    k_tsplit<<<dim3(DD / 32,  DD / 32), dim3(32, 8)>>>(Wq, Wqth, Wqtl, DD, DD);
    k_tsplit<<<dim3(KVD / 32, DD / 32), dim3(32, 8)>>>(Wk, Wkth, Wktl, DD, KVD);
    k_tsplit<<<dim3(KVD / 32, DD / 32), dim3(32, 8)>>>(Wv, Wvth_, Wvtl_, DD, KVD);
    k_tsplit<<<dim3(DD / 32,  DD / 32), dim3(32, 8)>>>(Wo, Woth, Wotl, DD, DD);

    // ---- Q projection -> split bf16 ----
    gemm_tc<<<dim3(DD / BN, MTOT / BM, 1), 256, GEMM_SMEM>>>(
        qh, ql, Wqth, Wqtl, bq, nullptr, Qsh, Qsl, 1,
        Wqth, Wqtl, bq, nullptr, Qsh, Qsl, 1, MTOT, DD, DD);

    // ---- K (split natural) and V (split transposed) projections ----
    gemm_tc<<<dim3(KVD / BN, MTOT / BM, 2), 256, GEMM_SMEM>>>(
        kvh, kvl, Wkth, Wktl, bk, nullptr, Ksh, Ksl, 1,
        Wvth_, Wvtl_, bv, nullptr, Vth, Vtl, 2, MTOT, KVD, DD);

    // ---- tensor-core attention -> Ao split ----
    attn_mma<<<dim3(SS / 128, BB * QH), 256, ATTN_SMEM>>>(
        Qsh, Qsl, Ksh, Ksl, Vth, Vtl, Aoh, Aol);

    // ---- output projection (fp32 out) ----
    gemm_tc<<<dim3(DD / BN, MTOT / BM, 1), 256, GEMM_SMEM>>>(
        Aoh, Aol, Woth, Wotl, bo, out, nullptr, nullptr, 0,
        Woth, Wotl, bo, out, nullptr, nullptr, 0, MTOT, DD, DD);
}

// round 9
// speedup vs baseline: 2.5689x; 1.0140x over previous
#include <cuda_runtime.h>
#include <cuda_bf16.h>
#include <cstdint>

// Problem constants
#define BB   2
#define SS   1024
#define DD   2048
#define QH   32
#define KH   8
#define HD   64
#define KVD  (KH*HD)        // 512
#define MTOT (BB*SS)        // 2048

typedef __nv_bfloat16 bf16;
typedef __nv_bfloat162 bf162;

// ---------------- scratch (device globals; alignas(16) for cp.async) -------
__device__ alignas(16) bf16 g_qh[MTOT * DD],  g_ql[MTOT * DD];
__device__ alignas(16) bf16 g_kvh[MTOT * DD], g_kvl[MTOT * DD];
__device__ alignas(16) bf16 g_Wqt_h[DD * DD],  g_Wqt_l[DD * DD];     // [n][k]
__device__ alignas(16) bf16 g_Wkt_h[KVD * DD], g_Wkt_l[KVD * DD];
__device__ alignas(16) bf16 g_Wvt_h[KVD * DD], g_Wvt_l[KVD * DD];
__device__ alignas(16) bf16 g_Wot_h[DD * DD],  g_Wot_l[DD * DD];
__device__ alignas(16) bf16 g_Qsh[MTOT * DD],  g_Qsl[MTOT * DD];     // Q proj split
__device__ alignas(16) bf16 g_Ksh[MTOT * KVD], g_Ksl[MTOT * KVD];    // K proj split
__device__ alignas(16) bf16 g_Vth[BB * KVD * SS], g_Vtl[BB * KVD * SS]; // V^T [b*512+d][s]
__device__ alignas(16) bf16 g_Aoh[MTOT * DD], g_Aol[MTOT * DD];

__device__ __forceinline__ void split_bf16(float v, bf16& h, bf16& l) {
    h = __float2bfloat16_rn(v);
    l = __float2bfloat16_rn(v - __bfloat162float(h));
}
__device__ __forceinline__ uint32_t pack2(bf16 a, bf16 b) {
    bf162 t = __halves2bfloat162(a, b);
    return *(uint32_t*)&t;
}

// ---------------- convert kernels ----------------
__global__ void k_split(const float* __restrict__ in, bf16* __restrict__ hi,
                        bf16* __restrict__ lo, int n)
{
    int i = (blockIdx.x * blockDim.x + threadIdx.x) * 4;
    if (i >= n) return;
    float4 v = *(const float4*)&in[i];
    bf16 h0, l0, h1, l1, h2, l2, h3, l3;
    split_bf16(v.x, h0, l0); split_bf16(v.y, h1, l1);
    split_bf16(v.z, h2, l2); split_bf16(v.w, h3, l3);
    *(bf162*)&hi[i]     = __halves2bfloat162(h0, h1);
    *(bf162*)&hi[i + 2] = __halves2bfloat162(h2, h3);
    *(bf162*)&lo[i]     = __halves2bfloat162(l0, l1);
    *(bf162*)&lo[i + 2] = __halves2bfloat162(l2, l3);
}

__global__ void k_tsplit(const float* __restrict__ in, bf16* __restrict__ hi,
                         bf16* __restrict__ lo, int R, int C)
{
    __shared__ float t[32][33];
    int r0 = blockIdx.y * 32, c0 = blockIdx.x * 32;
#pragma unroll
    for (int i = 0; i < 4; i++) {
        int r = r0 + threadIdx.y + i * 8;
        t[threadIdx.y + i * 8][threadIdx.x] = in[(size_t)r * C + c0 + threadIdx.x];
    }
    __syncthreads();
#pragma unroll
    for (int i = 0; i < 4; i++) {
        int c = c0 + threadIdx.y + i * 8;
        float v = t[threadIdx.x][threadIdx.y + i * 8];
        bf16 h, l; split_bf16(v, h, l);
        hi[(size_t)c * R + r0 + threadIdx.x] = h;
        lo[(size_t)c * R + r0 + threadIdx.x] = l;
    }
}

// ============================================================================
// Tensor-core GEMM on pre-split bf16. Epilogue modes:
//   0: fp32 C      1: split bf16 natural Ch/Cl      2: split bf16 V-transposed
// ============================================================================
#define BM 128
#define BN 128
#define BK 32
#define KSTR 40
#define TILE_BF (BM * KSTR)
#define STAGE_BF (4 * TILE_BF)
#define GEMM_SMEM (2 * STAGE_BF * 2)

__device__ __forceinline__ void cpa16(void* dst, const void* src) {
    uint32_t d = (uint32_t)__cvta_generic_to_shared(dst);
    asm volatile("cp.async.ca.shared.global [%0], [%1], 16;" :: "r"(d), "l"(src));
}
__device__ __forceinline__ void ldmx4(uint32_t* r, const void* p) {
    uint32_t addr = (uint32_t)__cvta_generic_to_shared(p);
    asm volatile("ldmatrix.sync.aligned.m8n8.x4.shared.b16 {%0,%1,%2,%3}, [%4];"
                 : "=r"(r[0]), "=r"(r[1]), "=r"(r[2]), "=r"(r[3]) : "r"(addr));
}
__device__ __forceinline__ void mma16816(float* c, const uint32_t* a, const uint32_t* b) {
    asm volatile("mma.sync.aligned.m16n8k16.row.col.f32.bf16.bf16.f32 "
                 "{%0,%1,%2,%3}, {%4,%5,%6,%7}, {%8,%9}, {%0,%1,%2,%3};"
                 : "+f"(c[0]), "+f"(c[1]), "+f"(c[2]), "+f"(c[3])
                 : "r"(a[0]), "r"(a[1]), "r"(a[2]), "r"(a[3]),
                   "r"(b[0]), "r"(b[1]));
}

__device__ __forceinline__ void stage_tiles(
    bf16* base, const bf16* Ah, const bf16* Al, const bf16* Bh, const bf16* Bl,
    int row0, int col0, int kt, int K, int tid)
{
    bf16* pAh = base;               bf16* pAl = base + TILE_BF;
    bf16* pBh = base + 2 * TILE_BF; bf16* pBl = base + 3 * TILE_BF;
#pragma unroll
    for (int p = 0; p < 2; p++) {
        int c   = tid + p * 256;
        int r   = c >> 2;
        int off = (c & 3) * 8;
        const size_t ga = (size_t)(row0 + r) * K + kt + off;
        const size_t gb = (size_t)(col0 + r) * K + kt + off;
        const int so = r * KSTR + off;
        cpa16(pAh + so, Ah + ga);
        cpa16(pAl + so, Al + ga);
        cpa16(pBh + so, Bh + gb);
        cpa16(pBl + so, Bl + gb);
    }
}

__global__ __launch_bounds__(256, 2)
void gemm_tc(const bf16* __restrict__ Ah, const bf16* __restrict__ Al,
             const bf16* __restrict__ B0h, const bf16* __restrict__ B0l,
             const float* __restrict__ b0, float* __restrict__ C0,
             bf16* __restrict__ C0h, bf16* __restrict__ C0l, int mode0,
             const bf16* __restrict__ B1h, const bf16* __restrict__ B1l,
             const float* __restrict__ b1, float* __restrict__ C1,
             bf16* __restrict__ C1h, bf16* __restrict__ C1l, int mode1,
             int M, int N, int K)
{
    const bf16* Bh   = blockIdx.z ? B1h : B0h;
    const bf16* Bl   = blockIdx.z ? B1l : B0l;
    const float* bias = blockIdx.z ? b1 : b0;
    float* C   = blockIdx.z ? C1 : C0;
    bf16*  Ch  = blockIdx.z ? C1h : C0h;
    bf16*  Cl  = blockIdx.z ? C1l : C0l;
    const int mode = blockIdx.z ? mode1 : mode0;

    extern __shared__ bf16 smem[];

    const int tid  = threadIdx.x;
    const int lane = tid & 31;
    const int wid  = tid >> 5;
    const int wm   = wid & 1;
    const int wn   = wid >> 1;
    const int row0 = blockIdx.y * BM;
    const int col0 = blockIdx.x * BN;

    float acc[4][4][4];
#pragma unroll
    for (int i = 0; i < 4; i++)
#pragma unroll
        for (int j = 0; j < 4; j++)
#pragma unroll
            for (int k = 0; k < 4; k++) acc[i][j][k] = 0.f;

    const int a_r = lane & 15;
    const int a_k = (lane >> 4) << 3;
    const int b_r = (lane & 7) | ((lane & 16) >> 1);
    const int b_k = lane & 8;

    const int nt = K / BK;

    stage_tiles(smem, Ah, Al, Bh, Bl, row0, col0, 0, K, tid);
    asm volatile("cp.async.commit_group;");

    for (int t = 0; t < nt; t++) {
        if (t + 1 < nt)
            stage_tiles(smem + ((t + 1) & 1) * STAGE_BF,
                        Ah, Al, Bh, Bl, row0, col0, (t + 1) * BK, K, tid);
        asm volatile("cp.async.commit_group;");
        asm volatile("cp.async.wait_group 1;");
        __syncthreads();

        bf16* base = smem + (t & 1) * STAGE_BF;
        bf16* pAh = base;             bf16* pAl = base + TILE_BF;
        bf16* pBh = base + 2*TILE_BF; bf16* pBl = base + 3*TILE_BF;

#pragma unroll
        for (int kk = 0; kk < BK; kk += 16) {
            uint32_t af[4][4], bh[2][4], bl[2][4];
#pragma unroll
            for (int i = 0; i < 4; i++)
                ldmx4(af[i], pAh + (wm * 64 + i * 16 + a_r) * KSTR + kk + a_k);
#pragma unroll
            for (int j = 0; j < 2; j++)
                ldmx4(bh[j], pBh + (wn * 32 + j * 16 + b_r) * KSTR + kk + b_k);
#pragma unroll
            for (int j = 0; j < 2; j++)
                ldmx4(bl[j], pBl + (wn * 32 + j * 16 + b_r) * KSTR + kk + b_k);

#pragma unroll
            for (int i = 0; i < 4; i++)
#pragma unroll
                for (int j = 0; j < 4; j++)
                    mma16816(acc[i][j], af[i], &bh[j >> 1][(j & 1) * 2]);
#pragma unroll
            for (int i = 0; i < 4; i++)
#pragma unroll
                for (int j = 0; j < 4; j++)
                    mma16816(acc[i][j], af[i], &bl[j >> 1][(j & 1) * 2]);
#pragma unroll
            for (int i = 0; i < 4; i++)
                ldmx4(af[i], pAl + (wm * 64 + i * 16 + a_r) * KSTR + kk + a_k);
#pragma unroll
            for (int i = 0; i < 4; i++)
#pragma unroll
                for (int j = 0; j < 4; j++)
                    mma16816(acc[i][j], af[i], &bh[j >> 1][(j & 1) * 2]);
        }
        __syncthreads();
    }

    // epilogue
#pragma unroll
    for (int i = 0; i < 4; i++) {
        int gr = row0 + wm * 64 + i * 16 + (lane >> 2);
#pragma unroll
        for (int j = 0; j < 4; j++) {
            int gc = col0 + wn * 32 + j * 8 + (lane & 3) * 2;
            float bx = bias[gc], by = bias[gc + 1];
            float v0 = acc[i][j][0] + bx, v1 = acc[i][j][1] + by;
            float v2 = acc[i][j][2] + bx, v3 = acc[i][j][3] + by;
            if (mode == 0) {
                *(float2*)&C[(size_t)gr * N + gc]       = make_float2(v0, v1);
                *(float2*)&C[(size_t)(gr + 8) * N + gc] = make_float2(v2, v3);
            } else if (mode == 1) {
                bf16 h0,l0,h1,l1,h2,l2,h3,l3;
                split_bf16(v0,h0,l0); split_bf16(v1,h1,l1);
                split_bf16(v2,h2,l2); split_bf16(v3,h3,l3);
                *(uint32_t*)&Ch[(size_t)gr * N + gc]       = pack2(h0, h1);
                *(uint32_t*)&Cl[(size_t)gr * N + gc]       = pack2(l0, l1);
                *(uint32_t*)&Ch[(size_t)(gr + 8) * N + gc] = pack2(h2, h3);
                *(uint32_t*)&Cl[(size_t)(gr + 8) * N + gc] = pack2(l2, l3);
            } else {
                // V-transposed: Vt[(b*KVD + gc)][s], b = gr>>10, s = gr&1023
                int b0i = gr >> 10, s0 = gr & 1023;
                int b1i = (gr + 8) >> 10, s1 = (gr + 8) & 1023;
                bf16 h, l;
                size_t i00 = ((size_t)b0i * KVD + gc) * SS + s0;
                size_t i01 = ((size_t)b0i * KVD + gc + 1) * SS + s0;
                size_t i10 = ((size_t)b1i * KVD + gc) * SS + s1;
                size_t i11 = ((size_t)b1i * KVD + gc + 1) * SS + s1;
                split_bf16(v0, h, l); Ch[i00] = h; Cl[i00] = l;
                split_bf16(v1, h, l); Ch[i01] = h; Cl[i01] = l;
                split_bf16(v2, h, l); Ch[i10] = h; Cl[i10] = l;
                split_bf16(v3, h, l); Ch[i11] = h; Cl[i11] = l;
            }
        }
    }
}

// ============================================================================
// Tensor-core causal GQA flash attention, double-buffered K/V pipeline.
// Block: 128 q-rows x one (b,h). 8 warps, m-split (16 rows each, full N).
// ============================================================================
#define QSTR 72                          // smem row stride (bf16): 144 B
#define KVSTG (4 * 64 * QSTR)            // elems per K/V stage (Kh,Kl,Vh,Vl)
#define ATTN_SMEM (2 * KVSTG * 2)        // 73728 B (Q staging overlays stage 0)

__global__ __launch_bounds__(256)
void attn_mma(const bf16* __restrict__ Qh, const bf16* __restrict__ Ql,
              const bf16* __restrict__ Kh, const bf16* __restrict__ Kl,
              const bf16* __restrict__ Vth, const bf16* __restrict__ Vtl,
              bf16* __restrict__ Aoh, bf16* __restrict__ Aol)
{
    extern __shared__ bf16 sm[];
    // Q staging overlays K/V stage 0 (consumed into regs before pipeline starts)
    bf16* sQh = sm;                      // [128][QSTR]
    bf16* sQl = sm + 128 * QSTR;

    const int tid = threadIdx.x, lane = tid & 31, wid = tid >> 5;
    const int y  = blockIdx.x;           // q tile 0..7
    const int bh = blockIdx.y;
    const int b  = bh >> 5, h = bh & 31, kh = h >> 2;
    const int qtok0 = b * SS + y * 128;

    const int a_r = lane & 15;
    const int a_k = (lane >> 4) << 3;
    const int b_r = (lane & 7) | ((lane & 16) >> 1);
    const int b_k = lane & 8;

    // ---- stage Q tile (128 rows x 64 d, hi+lo) ----
#pragma unroll
    for (int p = 0; p < 4; p++) {
        int c = tid + p * 256;           // 0..1023
        int r = c >> 3, off = (c & 7) * 8;
        const size_t g = (size_t)(qtok0 + r) * DD + h * HD + off;
        cpa16(sQh + r * QSTR + off, Qh + g);
        cpa16(sQl + r * QSTR + off, Ql + g);
    }
    asm volatile("cp.async.commit_group;");
    asm volatile("cp.async.wait_group 0;");
    __syncthreads();

    // Q a-frags to registers (4 k-chunks of 16)
    uint32_t qah[4][4], qal[4][4];
#pragma unroll
    for (int kk = 0; kk < 4; kk++) {
        ldmx4(qah[kk], sQh + (wid * 16 + a_r) * QSTR + kk * 16 + a_k);
        ldmx4(qal[kk], sQl + (wid * 16 + a_r) * QSTR + kk * 16 + a_k);
    }
    __syncthreads();   // Q smem region (stage 0) now free for K/V

    float oacc[8][4];
#pragma unroll
    for (int f = 0; f < 8; f++)
#pragma unroll
        for (int e = 0; e < 4; e++) oacc[f][e] = 0.f;
    float mA = -1e30f, mB = -1e30f, lA = 0.f, lB = 0.f;

    const int qrowA = y * 128 + wid * 16 + (lane >> 2);   // seq idx, rows e0/e1
    const int jend = 2 * y + 1;

    // K/V staging into stage s: K [64 kc][64 d] hi/lo, Vt [64 d][64 kc] hi/lo
    auto stage_kv = [&](int s, int j) {
        bf16* base = sm + s * KVSTG;
        bf16* pKh = base;
        bf16* pKl = base + 64 * QSTR;
        bf16* pVh = base + 128 * QSTR;
        bf16* pVl = base + 192 * QSTR;
        const int ktok0 = b * SS + j * 64;
#pragma unroll
        for (int p = 0; p < 2; p++) {
            int c = tid + p * 256;       // 0..511
            int r = c >> 3, off = (c & 7) * 8;
            const size_t gk = (size_t)(ktok0 + r) * KVD + kh * HD + off;
            cpa16(pKh + r * QSTR + off, Kh + gk);
            cpa16(pKl + r * QSTR + off, Kl + gk);
            const size_t gv = ((size_t)b * KVD + kh * HD + r) * SS + j * 64 + off;
            cpa16(pVh + r * QSTR + off, Vth + gv);
            cpa16(pVl + r * QSTR + off, Vtl + gv);
        }
    };

    // ---- prologue: stage tile 0 into buffer 0 ----
    stage_kv(0, 0);
    asm volatile("cp.async.commit_group;");

    for (int j = 0; j <= jend; j++) {
        if (j + 1 <= jend)
            stage_kv((j + 1) & 1, j + 1);
        asm volatile("cp.async.commit_group;");
        asm volatile("cp.async.wait_group 1;");
        __syncthreads();

        bf16* base = sm + (j & 1) * KVSTG;
        bf16* sKh = base;
        bf16* sKl = base + 64 * QSTR;
        bf16* sVh = base + 128 * QSTR;
        bf16* sVl = base + 192 * QSTR;

        if (j * 64 <= y * 128 + wid * 16 + 15) {   // warp has unmasked cols
            // ---- S = Q K^T, 3-term split ----
            float sacc[8][4];
#pragma unroll
            for (int f = 0; f < 8; f++)
#pragma unroll
                for (int e = 0; e < 4; e++) sacc[f][e] = 0.f;

            uint32_t kb[4][4];
#pragma unroll
            for (int kk = 0; kk < 4; kk++) {
#pragma unroll
                for (int nb = 0; nb < 4; nb++)
                    ldmx4(kb[nb], sKh + (nb * 16 + b_r) * QSTR + kk * 16 + b_k);
#pragma unroll
                for (int f = 0; f < 8; f++)
                    mma16816(sacc[f], qah[kk], &kb[f >> 1][(f & 1) * 2]);
#pragma unroll
                for (int f = 0; f < 8; f++)
                    mma16816(sacc[f], qal[kk], &kb[f >> 1][(f & 1) * 2]);
#pragma unroll
                for (int nb = 0; nb < 4; nb++)
                    ldmx4(kb[nb], sKl + (nb * 16 + b_r) * QSTR + kk * 16 + b_k);
#pragma unroll
                for (int f = 0; f < 8; f++)
                    mma16816(sacc[f], qah[kk], &kb[f >> 1][(f & 1) * 2]);
            }

            // ---- scale + causal mask ----
            const bool diag = (j >= 2 * y);
#pragma unroll
            for (int f = 0; f < 8; f++)
#pragma unroll
                for (int e = 0; e < 4; e++) {
                    float v = sacc[f][e] * 0.125f;
                    if (diag) {
                        int kg = j * 64 + f * 8 + (lane & 3) * 2 + (e & 1);
                        int qg = qrowA + (e >> 1) * 8;
                        if (kg > qg) v = -1e30f;
                    }
                    sacc[f][e] = v;
                }

            // ---- online softmax (rows A: e0/e1, rows B: e2/e3) ----
            float tmA = -1e30f, tmB = -1e30f;
#pragma unroll
            for (int f = 0; f < 8; f++) {
                tmA = fmaxf(tmA, fmaxf(sacc[f][0], sacc[f][1]));
                tmB = fmaxf(tmB, fmaxf(sacc[f][2], sacc[f][3]));
            }
            tmA = fmaxf(tmA, __shfl_xor_sync(0xffffffffu, tmA, 1));
            tmA = fmaxf(tmA, __shfl_xor_sync(0xffffffffu, tmA, 2));
            tmB = fmaxf(tmB, __shfl_xor_sync(0xffffffffu, tmB, 1));
            tmB = fmaxf(tmB, __shfl_xor_sync(0xffffffffu, tmB, 2));
            float mnA = fmaxf(mA, tmA), mnB = fmaxf(mB, tmB);
            float alA = __expf(mA - mnA), alB = __expf(mB - mnB);
            mA = mnA; mB = mnB;

            float suA = 0.f, suB = 0.f;
#pragma unroll
            for (int f = 0; f < 8; f++) {
                float p0 = __expf(sacc[f][0] - mA);
                float p1 = __expf(sacc[f][1] - mA);
                float p2 = __expf(sacc[f][2] - mB);
                float p3 = __expf(sacc[f][3] - mB);
                suA += p0 + p1; suB += p2 + p3;
                sacc[f][0] = p0; sacc[f][1] = p1; sacc[f][2] = p2; sacc[f][3] = p3;
            }
            suA += __shfl_xor_sync(0xffffffffu, suA, 1);
            suA += __shfl_xor_sync(0xffffffffu, suA, 2);
            suB += __shfl_xor_sync(0xffffffffu, suB, 1);
            suB += __shfl_xor_sync(0xffffffffu, suB, 2);
            lA = lA * alA + suA; lB = lB * alB + suB;

#pragma unroll
            for (int f = 0; f < 8; f++) {
                oacc[f][0] *= alA; oacc[f][1] *= alA;
                oacc[f][2] *= alB; oacc[f][3] *= alB;
            }

            // ---- O += P V (per kc-chunk: pack P, MMA with Vt frags) ----
            uint32_t vb[4][4];
#pragma unroll
            for (int c = 0; c < 4; c++) {
                const int f0 = 2 * c, f1 = 2 * c + 1;
                bf16 hh[8], ll[8];
                split_bf16(sacc[f0][0], hh[0], ll[0]);
                split_bf16(sacc[f0][1], hh[1], ll[1]);
                split_bf16(sacc[f0][2], hh[2], ll[2]);
                split_bf16(sacc[f0][3], hh[3], ll[3]);
                split_bf16(sacc[f1][0], hh[4], ll[4]);
                split_bf16(sacc[f1][1], hh[5], ll[5]);
                split_bf16(sacc[f1][2], hh[6], ll[6]);
                split_bf16(sacc[f1][3], hh[7], ll[7]);
                uint32_t pah[4] = { pack2(hh[0], hh[1]), pack2(hh[2], hh[3]),
                                    pack2(hh[4], hh[5]), pack2(hh[6], hh[7]) };
                uint32_t pal[4] = { pack2(ll[0], ll[1]), pack2(ll[2], ll[3]),
                                    pack2(ll[4], ll[5]), pack2(ll[6], ll[7]) };
#pragma unroll
                for (int nb = 0; nb < 4; nb++)
                    ldmx4(vb[nb], sVh + (nb * 16 + b_r) * QSTR + c * 16 + b_k);
#pragma unroll
                for (int f = 0; f < 8; f++)
                    mma16816(oacc[f], pah, &vb[f >> 1][(f & 1) * 2]);
#pragma unroll
                for (int f = 0; f < 8; f++)
                    mma16816(oacc[f], pal, &vb[f >> 1][(f & 1) * 2]);
#pragma unroll
                for (int nb = 0; nb < 4; nb++)
                    ldmx4(vb[nb], sVl + (nb * 16 + b_r) * QSTR + c * 16 + b_k);
#pragma unroll
                for (int f = 0; f < 8; f++)
                    mma16816(oacc[f], pah, &vb[f >> 1][(f & 1) * 2]);
            }
        }
        __syncthreads();   // all warps done with buffer (j&1) before restaging
    }

    // ---- normalize + split-write O ----
    const float ivA = 1.f / lA, ivB = 1.f / lB;
    const int tokA = qtok0 + wid * 16 + (lane >> 2);
#pragma unroll
    for (int f = 0; f < 8; f++) {
        int col = h * HD + f * 8 + (lane & 3) * 2;
        bf16 h0,l0,h1,l1,h2,l2,h3,l3;
        split_bf16(oacc[f][0] * ivA, h0, l0);
        split_bf16(oacc[f][1] * ivA, h1, l1);
        split_bf16(oacc[f][2] * ivB, h2, l2);
        split_bf16(oacc[f][3] * ivB, h3, l3);
        *(uint32_t*)&Aoh[(size_t)tokA * DD + col]       = pack2(h0, h1);
        *(uint32_t*)&Aol[(size_t)tokA * DD + col]       = pack2(l0, l1);
        *(uint32_t*)&Aoh[(size_t)(tokA + 8) * DD + col] = pack2(h2, h3);
        *(uint32_t*)&Aol[(size_t)(tokA + 8) * DD + col] = pack2(l2, l3);
    }
}

// ---------------- launcher ----------------
extern "C" void kernel_launch(void* const* d_in, const int* in_sizes, int n_in,
                              void* d_out, int out_size)
{
    const float* q  = (const float*)d_in[0];
    const float* kv = (const float*)d_in[1];
    // d_in[2] = mask (causal, static) -- unused
    const float* Wq = (const float*)d_in[3];
    const float* bq = (const float*)d_in[4];
    const float* Wk = (const float*)d_in[5];
    const float* bk = (const float*)d_in[6];
    const float* Wv = (const float*)d_in[7];
    const float* bv = (const float*)d_in[8];
    const float* Wo = (const float*)d_in[9];
    const float* bo = (const float*)d_in[10];
    float* out = (float*)d_out;

    bf16 *qh, *ql, *kvh, *kvl, *Wqth, *Wqtl, *Wkth, *Wktl, *Wvth_, *Wvtl_, *Woth, *Wotl;
    bf16 *Qsh, *Qsl, *Ksh, *Ksl, *Vth, *Vtl, *Aoh, *Aol;
    cudaGetSymbolAddress((void**)&qh,  g_qh);   cudaGetSymbolAddress((void**)&ql,  g_ql);
    cudaGetSymbolAddress((void**)&kvh, g_kvh);  cudaGetSymbolAddress((void**)&kvl, g_kvl);
    cudaGetSymbolAddress((void**)&Wqth, g_Wqt_h); cudaGetSymbolAddress((void**)&Wqtl, g_Wqt_l);
    cudaGetSymbolAddress((void**)&Wkth, g_Wkt_h); cudaGetSymbolAddress((void**)&Wktl, g_Wkt_l);
    cudaGetSymbolAddress((void**)&Wvth_, g_Wvt_h); cudaGetSymbolAddress((void**)&Wvtl_, g_Wvt_l);
    cudaGetSymbolAddress((void**)&Woth, g_Wot_h); cudaGetSymbolAddress((void**)&Wotl, g_Wot_l);
    cudaGetSymbolAddress((void**)&Qsh, g_Qsh);  cudaGetSymbolAddress((void**)&Qsl, g_Qsl);
    cudaGetSymbolAddress((void**)&Ksh, g_Ksh);  cudaGetSymbolAddress((void**)&Ksl, g_Ksl);
    cudaGetSymbolAddress((void**)&Vth, g_Vth);  cudaGetSymbolAddress((void**)&Vtl, g_Vtl);
    cudaGetSymbolAddress((void**)&Aoh, g_Aoh);  cudaGetSymbolAddress((void**)&Aol, g_Aol);

    cudaFuncSetAttribute(gemm_tc,
                         cudaFuncAttributeMaxDynamicSharedMemorySize, GEMM_SMEM);
    cudaFuncSetAttribute(attn_mma,
                         cudaFuncAttributeMaxDynamicSharedMemorySize, ATTN_SMEM);

    // ---- converts ----
    k_split<<<(MTOT * DD / 4 + 255) / 256, 256>>>(q,  qh,  ql,  MTOT * DD);
    k_split<<<(MTOT * DD / 4 + 255) / 256, 256>>>(kv, kvh, kvl, MTOT * DD);
    k_tsplit<<<dim3(DD / 32,  DD / 32), dim3(32, 8)>>>(Wq, Wqth, Wqtl, DD, DD);
    k_tsplit<<<dim3(KVD / 32, DD / 32), dim3(32, 8)>>>(Wk, Wkth, Wktl, DD, KVD);
    k_tsplit<<<dim3(KVD / 32, DD / 32), dim3(32, 8)>>>(Wv, Wvth_, Wvtl_, DD, KVD);
    k_tsplit<<<dim3(DD / 32,  DD / 32), dim3(32, 8)>>>(Wo, Woth, Wotl, DD, DD);

    // ---- Q projection -> split bf16 ----
    gemm_tc<<<dim3(DD / BN, MTOT / BM, 1), 256, GEMM_SMEM>>>(
        qh, ql, Wqth, Wqtl, bq, nullptr, Qsh, Qsl, 1,
        Wqth, Wqtl, bq, nullptr, Qsh, Qsl, 1, MTOT, DD, DD);

    // ---- K (split natural) and V (split transposed) projections ----
    gemm_tc<<<dim3(KVD / BN, MTOT / BM, 2), 256, GEMM_SMEM>>>(
        kvh, kvl, Wkth, Wktl, bk, nullptr, Ksh, Ksl, 1,
        Wvth_, Wvtl_, bv, nullptr, Vth, Vtl, 2, MTOT, KVD, DD);

    // ---- tensor-core attention -> Ao split ----
    attn_mma<<<dim3(SS / 128, BB * QH), 256, ATTN_SMEM>>>(
        Qsh, Qsl, Ksh, Ksl, Vth, Vtl, Aoh, Aol);

    // ---- output projection (fp32 out) ----
    gemm_tc<<<dim3(DD / BN, MTOT / BM, 1), 256, GEMM_SMEM>>>(
        Aoh, Aol, Woth, Wotl, bo, out, nullptr, nullptr, 0,
        Woth, Wotl, bo, out, nullptr, nullptr, 0, MTOT, DD, DD);
}

// round 12
// speedup vs baseline: 2.6330x; 1.0249x over previous
#include <cuda_runtime.h>
#include <cuda_bf16.h>
#include <cstdint>

// Problem constants
#define BB   2
#define SS   1024
#define DD   2048
#define QH   32
#define KH   8
#define HD   64
#define KVD  (KH*HD)        // 512
#define MTOT (BB*SS)        // 2048

typedef __nv_bfloat16 bf16;
typedef __nv_bfloat162 bf162;

// ---------------- scratch (device globals; alignas(16) for cp.async) -------
__device__ alignas(16) bf16 g_qh[MTOT * DD],  g_ql[MTOT * DD];
__device__ alignas(16) bf16 g_kvh[MTOT * DD], g_kvl[MTOT * DD];
__device__ alignas(16) bf16 g_Wqt_h[DD * DD],  g_Wqt_l[DD * DD];     // [n][k]
__device__ alignas(16) bf16 g_Wkt_h[KVD * DD], g_Wkt_l[KVD * DD];
__device__ alignas(16) bf16 g_Wvt_h[KVD * DD], g_Wvt_l[KVD * DD];
__device__ alignas(16) bf16 g_Wot_h[DD * DD],  g_Wot_l[DD * DD];
__device__ alignas(16) bf16 g_Qsh[MTOT * DD],  g_Qsl[MTOT * DD];
__device__ alignas(16) bf16 g_Ksh[MTOT * KVD], g_Ksl[MTOT * KVD];
__device__ alignas(16) bf16 g_Vth[BB * KVD * SS], g_Vtl[BB * KVD * SS]; // V^T
__device__ alignas(16) bf16 g_Aoh[MTOT * DD], g_Aol[MTOT * DD];

__device__ __forceinline__ void split_bf16(float v, bf16& h, bf16& l) {
    h = __float2bfloat16_rn(v);
    l = __float2bfloat16_rn(v - __bfloat162float(h));
}
__device__ __forceinline__ uint32_t pack2(bf16 a, bf16 b) {
    bf162 t = __halves2bfloat162(a, b);
    return *(uint32_t*)&t;
}
// packed split of two floats: hp = pack2(bf(a), bf(b)), lp = pack2(residuals)
__device__ __forceinline__ void split2(float a, float b, uint32_t& hp, uint32_t& lp) {
    asm("cvt.rn.bf16x2.f32 %0, %1, %2;" : "=r"(hp) : "f"(b), "f"(a));
    float ha = __uint_as_float(hp << 16);
    float hb = __uint_as_float(hp & 0xFFFF0000u);
    float la = a - ha, lb = b - hb;
    asm("cvt.rn.bf16x2.f32 %0, %1, %2;" : "=r"(lp) : "f"(lb), "f"(la));
}
__device__ __forceinline__ void cpa16(void* dst, const void* src) {
    uint32_t d = (uint32_t)__cvta_generic_to_shared(dst);
    asm volatile("cp.async.ca.shared.global [%0], [%1], 16;" :: "r"(d), "l"(src));
}
__device__ __forceinline__ void ldmx4(uint32_t* r, const void* p) {
    uint32_t addr = (uint32_t)__cvta_generic_to_shared(p);
    asm volatile("ldmatrix.sync.aligned.m8n8.x4.shared.b16 {%0,%1,%2,%3}, [%4];"
                 : "=r"(r[0]), "=r"(r[1]), "=r"(r[2]), "=r"(r[3]) : "r"(addr));
}
__device__ __forceinline__ void mma16816(float* c, const uint32_t* a, const uint32_t* b) {
    asm volatile("mma.sync.aligned.m16n8k16.row.col.f32.bf16.bf16.f32 "
                 "{%0,%1,%2,%3}, {%4,%5,%6,%7}, {%8,%9}, {%0,%1,%2,%3};"
                 : "+f"(c[0]), "+f"(c[1]), "+f"(c[2]), "+f"(c[3])
                 : "r"(a[0]), "r"(a[1]), "r"(a[2]), "r"(a[3]),
                   "r"(b[0]), "r"(b[1]));
}

// ---------------- convert kernels (fused) ----------------
__global__ void k_split2in(const float* __restrict__ a, bf16* __restrict__ ah, bf16* __restrict__ al,
                           const float* __restrict__ b, bf16* __restrict__ bh, bf16* __restrict__ bl,
                           int n)
{
    const float* in = blockIdx.z ? b : a;
    bf16* hi = blockIdx.z ? bh : ah;
    bf16* lo = blockIdx.z ? bl : al;
    int i = (blockIdx.x * blockDim.x + threadIdx.x) * 4;
    if (i >= n) return;
    float4 v = *(const float4*)&in[i];
    uint32_t h0, l0, h1, l1;
    split2(v.x, v.y, h0, l0);
    split2(v.z, v.w, h1, l1);
    *(uint32_t*)&hi[i]     = h0; *(uint32_t*)&hi[i + 2] = h1;
    *(uint32_t*)&lo[i]     = l0; *(uint32_t*)&lo[i + 2] = l1;
}

// transpose + split, 4 weights in one launch (z selects). in fp32 [DD][C] -> [C][DD]
__global__ void k_tsplit4(const float* __restrict__ i0, bf16* __restrict__ h0, bf16* __restrict__ l0,
                          const float* __restrict__ i1, bf16* __restrict__ h1, bf16* __restrict__ l1,
                          const float* __restrict__ i2, bf16* __restrict__ h2, bf16* __restrict__ l2,
                          const float* __restrict__ i3, bf16* __restrict__ h3, bf16* __restrict__ l3)
{
    const int z = blockIdx.z;
    const float* in = (z == 0) ? i0 : (z == 1) ? i1 : (z == 2) ? i2 : i3;
    bf16* hi = (z == 0) ? h0 : (z == 1) ? h1 : (z == 2) ? h2 : h3;
    bf16* lo = (z == 0) ? l0 : (z == 1) ? l1 : (z == 2) ? l2 : l3;
    const int C = (z < 2) ? DD : KVD;
    const int R = DD;
    int r0 = blockIdx.y * 32, c0 = blockIdx.x * 32;
    if (c0 >= C) return;
    __shared__ float t[32][33];
#pragma unroll
    for (int i = 0; i < 4; i++) {
        int r = r0 + threadIdx.y + i * 8;
        t[threadIdx.y + i * 8][threadIdx.x] = in[(size_t)r * C + c0 + threadIdx.x];
    }
    __syncthreads();
#pragma unroll
    for (int i = 0; i < 4; i++) {
        int c = c0 + threadIdx.y + i * 8;
        float v = t[threadIdx.x][threadIdx.y + i * 8];
        bf16 h, l; split_bf16(v, h, l);
        hi[(size_t)c * R + r0 + threadIdx.x] = h;
        lo[(size_t)c * R + r0 + threadIdx.x] = l;
    }
}

// ============================================================================
// Tensor-core GEMM on pre-split bf16. Epilogue modes:
//   0: fp32 C   1: split bf16 natural Ch/Cl (with scale)   2: split bf16 V-T
// ============================================================================
#define BM 128
#define BN 128
#define BK 32
#define KSTR 40
#define TILE_BF (BM * KSTR)
#define STAGE_BF (4 * TILE_BF)
#define GEMM_SMEM (2 * STAGE_BF * 2)

__device__ __forceinline__ void stage_tiles(
    bf16* base, const bf16* Ah, const bf16* Al, const bf16* Bh, const bf16* Bl,
    int row0, int col0, int kt, int K, int tid)
{
    bf16* pAh = base;               bf16* pAl = base + TILE_BF;
    bf16* pBh = base + 2 * TILE_BF; bf16* pBl = base + 3 * TILE_BF;
#pragma unroll
    for (int p = 0; p < 2; p++) {
        int c   = tid + p * 256;
        int r   = c >> 2;
        int off = (c & 3) * 8;
        const size_t ga = (size_t)(row0 + r) * K + kt + off;
        const size_t gb = (size_t)(col0 + r) * K + kt + off;
        const int so = r * KSTR + off;
        cpa16(pAh + so, Ah + ga);
        cpa16(pAl + so, Al + ga);
        cpa16(pBh + so, Bh + gb);
        cpa16(pBl + so, Bl + gb);
    }
}

__global__ __launch_bounds__(256, 2)
void gemm_tc(const bf16* __restrict__ Ah, const bf16* __restrict__ Al,
             const bf16* __restrict__ B0h, const bf16* __restrict__ B0l,
             const float* __restrict__ b0, float* __restrict__ C0,
             bf16* __restrict__ C0h, bf16* __restrict__ C0l, int mode0,
             const bf16* __restrict__ B1h, const bf16* __restrict__ B1l,
             const float* __restrict__ b1, float* __restrict__ C1,
             bf16* __restrict__ C1h, bf16* __restrict__ C1l, int mode1,
             float scale, int M, int N, int K)
{
    const bf16* Bh   = blockIdx.z ? B1h : B0h;
    const bf16* Bl   = blockIdx.z ? B1l : B0l;
    const float* bias = blockIdx.z ? b1 : b0;
    float* C   = blockIdx.z ? C1 : C0;
    bf16*  Ch  = blockIdx.z ? C1h : C0h;
    bf16*  Cl  = blockIdx.z ? C1l : C0l;
    const int mode = blockIdx.z ? mode1 : mode0;

    extern __shared__ bf16 smem[];

    const int tid  = threadIdx.x;
    const int lane = tid & 31;
    const int wid  = tid >> 5;
    const int wm   = wid & 1;
    const int wn   = wid >> 1;
    const int row0 = blockIdx.y * BM;
    const int col0 = blockIdx.x * BN;

    float acc[4][4][4];
#pragma unroll
    for (int i = 0; i < 4; i++)
#pragma unroll
        for (int j = 0; j < 4; j++)
#pragma unroll
            for (int k = 0; k < 4; k++) acc[i][j][k] = 0.f;

    const int a_r = lane & 15;
    const int a_k = (lane >> 4) << 3;
    const int b_r = (lane & 7) | ((lane & 16) >> 1);
    const int b_k = lane & 8;

    const int nt = K / BK;

    stage_tiles(smem, Ah, Al, Bh, Bl, row0, col0, 0, K, tid);
    asm volatile("cp.async.commit_group;");

    for (int t = 0; t < nt; t++) {
        if (t + 1 < nt)
            stage_tiles(smem + ((t + 1) & 1) * STAGE_BF,
                        Ah, Al, Bh, Bl, row0, col0, (t + 1) * BK, K, tid);
        asm volatile("cp.async.commit_group;");
        asm volatile("cp.async.wait_group 1;");
        __syncthreads();

        bf16* base = smem + (t & 1) * STAGE_BF;
        bf16* pAh = base;             bf16* pAl = base + TILE_BF;
        bf16* pBh = base + 2*TILE_BF; bf16* pBl = base + 3*TILE_BF;

#pragma unroll
        for (int kk = 0; kk < BK; kk += 16) {
            uint32_t af[4][4], bh[2][4], bl[2][4];
#pragma unroll
            for (int i = 0; i < 4; i++)
                ldmx4(af[i], pAh + (wm * 64 + i * 16 + a_r) * KSTR + kk + a_k);
#pragma unroll
            for (int j = 0; j < 2; j++)
                ldmx4(bh[j], pBh + (wn * 32 + j * 16 + b_r) * KSTR + kk + b_k);
#pragma unroll
            for (int j = 0; j < 2; j++)
                ldmx4(bl[j], pBl + (wn * 32 + j * 16 + b_r) * KSTR + kk + b_k);

#pragma unroll
            for (int i = 0; i < 4; i++)
#pragma unroll
                for (int j = 0; j < 4; j++)
                    mma16816(acc[i][j], af[i], &bh[j >> 1][(j & 1) * 2]);
#pragma unroll
            for (int i = 0; i < 4; i++)
#pragma unroll
                for (int j = 0; j < 4; j++)
                    mma16816(acc[i][j], af[i], &bl[j >> 1][(j & 1) * 2]);
#pragma unroll
            for (int i = 0; i < 4; i++)
                ldmx4(af[i], pAl + (wm * 64 + i * 16 + a_r) * KSTR + kk + a_k);
#pragma unroll
            for (int i = 0; i < 4; i++)
#pragma unroll
                for (int j = 0; j < 4; j++)
                    mma16816(acc[i][j], af[i], &bh[j >> 1][(j & 1) * 2]);
        }
        __syncthreads();
    }

    // epilogue
#pragma unroll
    for (int i = 0; i < 4; i++) {
        int gr = row0 + wm * 64 + i * 16 + (lane >> 2);
#pragma unroll
        for (int j = 0; j < 4; j++) {
            int gc = col0 + wn * 32 + j * 8 + (lane & 3) * 2;
            float bx = bias[gc], by = bias[gc + 1];
            float v0 = (acc[i][j][0] + bx) * scale, v1 = (acc[i][j][1] + by) * scale;
            float v2 = (acc[i][j][2] + bx) * scale, v3 = (acc[i][j][3] + by) * scale;
            if (mode == 0) {
                *(float2*)&C[(size_t)gr * N + gc]       = make_float2(v0, v1);
                *(float2*)&C[(size_t)(gr + 8) * N + gc] = make_float2(v2, v3);
            } else if (mode == 1) {
                uint32_t hp0, lp0, hp1, lp1;
                split2(v0, v1, hp0, lp0);
                split2(v2, v3, hp1, lp1);
                *(uint32_t*)&Ch[(size_t)gr * N + gc]       = hp0;
                *(uint32_t*)&Cl[(size_t)gr * N + gc]       = lp0;
                *(uint32_t*)&Ch[(size_t)(gr + 8) * N + gc] = hp1;
                *(uint32_t*)&Cl[(size_t)(gr + 8) * N + gc] = lp1;
            } else {
                int b0i = gr >> 10, s0 = gr & 1023;
                int b1i = (gr + 8) >> 10, s1 = (gr + 8) & 1023;
                bf16 h, l;
                size_t i00 = ((size_t)b0i * KVD + gc) * SS + s0;
                size_t i01 = ((size_t)b0i * KVD + gc + 1) * SS + s0;
                size_t i10 = ((size_t)b1i * KVD + gc) * SS + s1;
                size_t i11 = ((size_t)b1i * KVD + gc + 1) * SS + s1;
                split_bf16(v0, h, l); Ch[i00] = h; Cl[i00] = l;
                split_bf16(v1, h, l); Ch[i01] = h; Cl[i01] = l;
                split_bf16(v2, h, l); Ch[i10] = h; Cl[i10] = l;
                split_bf16(v3, h, l); Ch[i11] = h; Cl[i11] = l;
            }
        }
    }
}

// ============================================================================
// Tensor-core causal GQA flash attention, double-buffered K/V pipeline.
// Q pre-scaled by 0.125 at projection; mask pass only on diagonal tiles.
// ============================================================================
#define QSTR 72
#define KVSTG (4 * 64 * QSTR)
#define ATTN_SMEM (2 * KVSTG * 2)

__global__ __launch_bounds__(256)
void attn_mma(const bf16* __restrict__ Qh, const bf16* __restrict__ Ql,
              const bf16* __restrict__ Kh, const bf16* __restrict__ Kl,
              const bf16* __restrict__ Vth, const bf16* __restrict__ Vtl,
              bf16* __restrict__ Aoh, bf16* __restrict__ Aol)
{
    extern __shared__ bf16 sm[];
    bf16* sQh = sm;
    bf16* sQl = sm + 128 * QSTR;

    const int tid = threadIdx.x, lane = tid & 31, wid = tid >> 5;
    const int y  = blockIdx.x;
    const int bh = blockIdx.y;
    const int b  = bh >> 5, h = bh & 31, kh = h >> 2;
    const int qtok0 = b * SS + y * 128;

    const int a_r = lane & 15;
    const int a_k = (lane >> 4) << 3;
    const int b_r = (lane & 7) | ((lane & 16) >> 1);
    const int b_k = lane & 8;

#pragma unroll
    for (int p = 0; p < 4; p++) {
        int c = tid + p * 256;
        int r = c >> 3, off = (c & 7) * 8;
        const size_t g = (size_t)(qtok0 + r) * DD + h * HD + off;
        cpa16(sQh + r * QSTR + off, Qh + g);
        cpa16(sQl + r * QSTR + off, Ql + g);
    }
    asm volatile("cp.async.commit_group;");
    asm volatile("cp.async.wait_group 0;");
    __syncthreads();

    uint32_t qah[4][4], qal[4][4];
#pragma unroll
    for (int kk = 0; kk < 4; kk++) {
        ldmx4(qah[kk], sQh + (wid * 16 + a_r) * QSTR + kk * 16 + a_k);
        ldmx4(qal[kk], sQl + (wid * 16 + a_r) * QSTR + kk * 16 + a_k);
    }
    __syncthreads();

    float oacc[8][4];
#pragma unroll
    for (int f = 0; f < 8; f++)
#pragma unroll
        for (int e = 0; e < 4; e++) oacc[f][e] = 0.f;
    float mA = -1e30f, mB = -1e30f, lA = 0.f, lB = 0.f;

    const int qrowA = y * 128 + wid * 16 + (lane >> 2);
    const int jend = 2 * y + 1;

    auto stage_kv = [&](int s, int j) {
        bf16* base = sm + s * KVSTG;
        bf16* pKh = base;
        bf16* pKl = base + 64 * QSTR;
        bf16* pVh = base + 128 * QSTR;
        bf16* pVl = base + 192 * QSTR;
        const int ktok0 = b * SS + j * 64;
#pragma unroll
        for (int p = 0; p < 2; p++) {
            int c = tid + p * 256;
            int r = c >> 3, off = (c & 7) * 8;
            const size_t gk = (size_t)(ktok0 + r) * KVD + kh * HD + off;
            cpa16(pKh + r * QSTR + off, Kh + gk);
            cpa16(pKl + r * QSTR + off, Kl + gk);
            const size_t gv = ((size_t)b * KVD + kh * HD + r) * SS + j * 64 + off;
            cpa16(pVh + r * QSTR + off, Vth + gv);
            cpa16(pVl + r * QSTR + off, Vtl + gv);
        }
    };

    stage_kv(0, 0);
    asm volatile("cp.async.commit_group;");

    for (int j = 0; j <= jend; j++) {
        if (j + 1 <= jend)
            stage_kv((j + 1) & 1, j + 1);
        asm volatile("cp.async.commit_group;");
        asm volatile("cp.async.wait_group 1;");
        __syncthreads();

        bf16* base = sm + (j & 1) * KVSTG;
        bf16* sKh = base;
        bf16* sKl = base + 64 * QSTR;
        bf16* sVh = base + 128 * QSTR;
        bf16* sVl = base + 192 * QSTR;

        if (j * 64 <= y * 128 + wid * 16 + 15) {
            // ---- S = Q K^T (Q pre-scaled), 3-term split ----
            float sacc[8][4];
#pragma unroll
            for (int f = 0; f < 8; f++)
#pragma unroll
                for (int e = 0; e < 4; e++) sacc[f][e] = 0.f;

            uint32_t kb[4][4];
#pragma unroll
            for (int kk = 0; kk < 4; kk++) {
#pragma unroll
                for (int nb = 0; nb < 4; nb++)
                    ldmx4(kb[nb], sKh + (nb * 16 + b_r) * QSTR + kk * 16 + b_k);
#pragma unroll
                for (int f = 0; f < 8; f++)
                    mma16816(sacc[f], qah[kk], &kb[f >> 1][(f & 1) * 2]);
#pragma unroll
                for (int f = 0; f < 8; f++)
                    mma16816(sacc[f], qal[kk], &kb[f >> 1][(f & 1) * 2]);
#pragma unroll
                for (int nb = 0; nb < 4; nb++)
                    ldmx4(kb[nb], sKl + (nb * 16 + b_r) * QSTR + kk * 16 + b_k);
#pragma unroll
                for (int f = 0; f < 8; f++)
                    mma16816(sacc[f], qah[kk], &kb[f >> 1][(f & 1) * 2]);
            }

            // ---- causal mask: only diagonal supertiles need it ----
            if (j >= 2 * y) {
#pragma unroll
                for (int f = 0; f < 8; f++)
#pragma unroll
                    for (int e = 0; e < 4; e++) {
                        int kg = j * 64 + f * 8 + (lane & 3) * 2 + (e & 1);
                        int qg = qrowA + (e >> 1) * 8;
                        if (kg > qg) sacc[f][e] = -1e30f;
                    }
            }

            // ---- online softmax (rows A: e0/e1, rows B: e2/e3) ----
            float tmA = -1e30f, tmB = -1e30f;
#pragma unroll
            for (int f = 0; f < 8; f++) {
                tmA = fmaxf(tmA, fmaxf(sacc[f][0], sacc[f][1]));
                tmB = fmaxf(tmB, fmaxf(sacc[f][2], sacc[f][3]));
            }
            tmA = fmaxf(tmA, __shfl_xor_sync(0xffffffffu, tmA, 1));
            tmA = fmaxf(tmA, __shfl_xor_sync(0xffffffffu, tmA, 2));
            tmB = fmaxf(tmB, __shfl_xor_sync(0xffffffffu, tmB, 1));
            tmB = fmaxf(tmB, __shfl_xor_sync(0xffffffffu, tmB, 2));
            float mnA = fmaxf(mA, tmA), mnB = fmaxf(mB, tmB);
            float alA = __expf(mA - mnA), alB = __expf(mB - mnB);
            mA = mnA; mB = mnB;

            float suA = 0.f, suB = 0.f;
#pragma unroll
            for (int f = 0; f < 8; f++) {
                float p0 = __expf(sacc[f][0] - mA);
                float p1 = __expf(sacc[f][1] - mA);
                float p2 = __expf(sacc[f][2] - mB);
                float p3 = __expf(sacc[f][3] - mB);
                suA += p0 + p1; suB += p2 + p3;
                sacc[f][0] = p0; sacc[f][1] = p1; sacc[f][2] = p2; sacc[f][3] = p3;
            }
            suA += __shfl_xor_sync(0xffffffffu, suA, 1);
            suA += __shfl_xor_sync(0xffffffffu, suA, 2);
            suB += __shfl_xor_sync(0xffffffffu, suB, 1);
            suB += __shfl_xor_sync(0xffffffffu, suB, 2);
            lA = lA * alA + suA; lB = lB * alB + suB;

#pragma unroll
            for (int f = 0; f < 8; f++) {
                oacc[f][0] *= alA; oacc[f][1] *= alA;
                oacc[f][2] *= alB; oacc[f][3] *= alB;
            }

            // ---- O += P V (per kc-chunk: packed split of P, MMA w/ Vt) ----
            uint32_t vb[4][4];
#pragma unroll
            for (int c = 0; c < 4; c++) {
                const int f0 = 2 * c, f1 = 2 * c + 1;
                uint32_t pah[4], pal[4];
                split2(sacc[f0][0], sacc[f0][1], pah[0], pal[0]);
                split2(sacc[f0][2], sacc[f0][3], pah[1], pal[1]);
                split2(sacc[f1][0], sacc[f1][1], pah[2], pal[2]);
                split2(sacc[f1][2], sacc[f1][3], pah[3], pal[3]);
#pragma unroll
                for (int nb = 0; nb < 4; nb++)
                    ldmx4(vb[nb], sVh + (nb * 16 + b_r) * QSTR + c * 16 + b_k);
#pragma unroll
                for (int f = 0; f < 8; f++)
                    mma16816(oacc[f], pah, &vb[f >> 1][(f & 1) * 2]);
#pragma unroll
                for (int f = 0; f < 8; f++)
                    mma16816(oacc[f], pal, &vb[f >> 1][(f & 1) * 2]);
#pragma unroll
                for (int nb = 0; nb < 4; nb++)
                    ldmx4(vb[nb], sVl + (nb * 16 + b_r) * QSTR + c * 16 + b_k);
#pragma unroll
                for (int f = 0; f < 8; f++)
                    mma16816(oacc[f], pah, &vb[f >> 1][(f & 1) * 2]);
            }
        }
        __syncthreads();
    }

    // ---- normalize + packed split-write O ----
    const float ivA = 1.f / lA, ivB = 1.f / lB;
    const int tokA = qtok0 + wid * 16 + (lane >> 2);
#pragma unroll
    for (int f = 0; f < 8; f++) {
        int col = h * HD + f * 8 + (lane & 3) * 2;
        uint32_t hpA, lpA, hpB, lpB;
        split2(oacc[f][0] * ivA, oacc[f][1] * ivA, hpA, lpA);
        split2(oacc[f][2] * ivB, oacc[f][3] * ivB, hpB, lpB);
        *(uint32_t*)&Aoh[(size_t)tokA * DD + col]       = hpA;
        *(uint32_t*)&Aol[(size_t)tokA * DD + col]       = lpA;
        *(uint32_t*)&Aoh[(size_t)(tokA + 8) * DD + col] = hpB;
        *(uint32_t*)&Aol[(size_t)(tokA + 8) * DD + col] = lpB;
    }
}

// ---------------- launcher ----------------
extern "C" void kernel_launch(void* const* d_in, const int* in_sizes, int n_in,
                              void* d_out, int out_size)
{
    const float* q  = (const float*)d_in[0];
    const float* kv = (const float*)d_in[1];
    // d_in[2] = mask (causal, static) -- unused
    const float* Wq = (const float*)d_in[3];
    const float* bq = (const float*)d_in[4];
    const float* Wk = (const float*)d_in[5];
    const float* bk = (const float*)d_in[6];
    const float* Wv = (const float*)d_in[7];
    const float* bv = (const float*)d_in[8];
    const float* Wo = (const float*)d_in[9];
    const float* bo = (const float*)d_in[10];
    float* out = (float*)d_out;

    bf16 *qh, *ql, *kvh, *kvl, *Wqth, *Wqtl, *Wkth, *Wktl, *Wvth_, *Wvtl_, *Woth, *Wotl;
    bf16 *Qsh, *Qsl, *Ksh, *Ksl, *Vth, *Vtl, *Aoh, *Aol;
    cudaGetSymbolAddress((void**)&qh,  g_qh);   cudaGetSymbolAddress((void**)&ql,  g_ql);
    cudaGetSymbolAddress((void**)&kvh, g_kvh);  cudaGetSymbolAddress((void**)&kvl, g_kvl);
    cudaGetSymbolAddress((void**)&Wqth, g_Wqt_h); cudaGetSymbolAddress((void**)&Wqtl, g_Wqt_l);
    cudaGetSymbolAddress((void**)&Wkth, g_Wkt_h); cudaGetSymbolAddress((void**)&Wktl, g_Wkt_l);
    cudaGetSymbolAddress((void**)&Wvth_, g_Wvt_h); cudaGetSymbolAddress((void**)&Wvtl_, g_Wvt_l);
    cudaGetSymbolAddress((void**)&Woth, g_Wot_h); cudaGetSymbolAddress((void**)&Wotl, g_Wot_l);
    cudaGetSymbolAddress((void**)&Qsh, g_Qsh);  cudaGetSymbolAddress((void**)&Qsl, g_Qsl);
    cudaGetSymbolAddress((void**)&Ksh, g_Ksh);  cudaGetSymbolAddress((void**)&Ksl, g_Ksl);
    cudaGetSymbolAddress((void**)&Vth, g_Vth);  cudaGetSymbolAddress((void**)&Vtl, g_Vtl);
    cudaGetSymbolAddress((void**)&Aoh, g_Aoh);  cudaGetSymbolAddress((void**)&Aol, g_Aol);

    cudaFuncSetAttribute(gemm_tc,
                         cudaFuncAttributeMaxDynamicSharedMemorySize, GEMM_SMEM);
    cudaFuncSetAttribute(attn_mma,
                         cudaFuncAttributeMaxDynamicSharedMemorySize, ATTN_SMEM);

    // ---- converts (2 fused launches) ----
    k_split2in<<<dim3(MTOT * DD / 4 / 256, 1, 2), 256>>>(
        q, qh, ql, kv, kvh, kvl, MTOT * DD);
    k_tsplit4<<<dim3(DD / 32, DD / 32, 4), dim3(32, 8)>>>(
        Wq, Wqth, Wqtl, Wo, Woth, Wotl, Wk, Wkth, Wktl, Wv, Wvth_, Wvtl_);

    // ---- Q projection -> split bf16, pre-scaled by 1/sqrt(HD)=0.125 ----
    gemm_tc<<<dim3(DD / BN, MTOT / BM, 1), 256, GEMM_SMEM>>>(
        qh, ql, Wqth, Wqtl, bq, nullptr, Qsh, Qsl, 1,
        Wqth, Wqtl, bq, nullptr, Qsh, Qsl, 1, 0.125f, MTOT, DD, DD);

    // ---- K (split natural) and V (split transposed) projections ----
    gemm_tc<<<dim3(KVD / BN, MTOT / BM, 2), 256, GEMM_SMEM>>>(
        kvh, kvl, Wkth, Wktl, bk, nullptr, Ksh, Ksl, 1,
        Wvth_, Wvtl_, bv, nullptr, Vth, Vtl, 2, 1.0f, MTOT, KVD, DD);

    // ---- tensor-core attention -> Ao split ----
    attn_mma<<<dim3(SS / 128, BB * QH), 256, ATTN_SMEM>>>(
        Qsh, Qsl, Ksh, Ksl, Vth, Vtl, Aoh, Aol);

    // ---- output projection (fp32 out) ----
    gemm_tc<<<dim3(DD / BN, MTOT / BM, 1), 256, GEMM_SMEM>>>(
        Aoh, Aol, Woth, Wotl, bo, out, nullptr, nullptr, 0,
        Woth, Wotl, bo, out, nullptr, nullptr, 0, 1.0f, MTOT, DD, DD);
}